// round 8
// baseline (speedup 1.0000x reference)
#include <cuda_runtime.h>
#include <math.h>

#define NPTS   65536
#define NN     34
#define KP     15
#define INF    64
#define OUTF   64
#define OFFD   60
#define EXTENTF 0.5f
#define PPB    8
#define TPB    512
#define NBLK   (NPTS / PPB)      // 8192
#define NI     (KP * INF)        // 960
#define NI4    (NI / 4)          // 240
#define SLOT_I4 (NI4 / PPB)      // 30 i4-blocks per slot

typedef unsigned long long u64;

// ---------------- device scratch (no allocations allowed) ----------------
__device__ __align__(16) float g_owT[NI4 * 64 * 4];   // blocked transpose of offset_weight (cols 60..63 = 0)
__device__ __align__(16) float g_wT [NI4 * 64 * 4];   // blocked transpose of weight
__device__ float g_psum  [NBLK * OUTF];
__device__ float g_psumsq[NBLK * OUTF];
__device__ __align__(16) float g_scale[OUTF];
__device__ __align__(16) float g_shift[OUTF];

// pure register-pair FFMA2: acc = a*b + acc, no pack/unpack movs
__device__ __forceinline__ void f2(u64 &acc, u64 a, u64 b) {
    asm("fma.rn.f32x2 %0, %1, %2, %0;" : "+l"(acc) : "l"(a), "l"(b));
}
__device__ __forceinline__ u64 splat2(float f) {
    u64 r; asm("mov.b64 %0, {%1, %1};" : "=l"(r) : "f"(f)); return r;
}
__device__ __forceinline__ float2 unpack2(u64 v) {
    float2 r; asm("mov.b64 {%0, %1}, %2;" : "=f"(r.x), "=f"(r.y) : "l"(v)); return r;
}

// ---------------- prep: blocked transposes of the two weight matrices ----------------
__global__ void prep_kernel(const float* __restrict__ ow, const float* __restrict__ w) {
    int t = blockIdx.x * blockDim.x + threadIdx.x;
    int stride = gridDim.x * blockDim.x;
    for (int idx = t; idx < NI * OFFD; idx += stride) {
        int i = idx / OFFD, d = idx - i * OFFD;
        g_owT[((i >> 2) * 64 + d) * 4 + (i & 3)] = ow[idx];
    }
    for (int idx = t; idx < NI * OUTF; idx += stride) {
        int i = idx / OUTF, o = idx - i * OUTF;
        g_wT[((i >> 2) * 64 + o) * 4 + (i & 3)] = w[idx];
    }
}

// weighted-row accumulate: 4 LDS.128 (paired) + 8 FFMA2, all in u64 domain
#define WROW_FMA(aa, fval) do {                                          \
    const ulonglong2* wr_ = (const ulonglong2*)&s_w[(ib + (aa)) * 20];   \
    u64 ff_ = splat2(fval);                                              \
    ulonglong2 q0 = wr_[0], q1 = wr_[1], q2 = wr_[2], q3 = wr_[3];       \
    f2(wf[0], q0.x, ff_); f2(wf[1], q0.y, ff_);                          \
    f2(wf[2], q1.x, ff_); f2(wf[3], q1.y, ff_);                          \
    f2(wf[4], q2.x, ff_); f2(wf[5], q2.y, ff_);                          \
    f2(wf[6], q3.x, ff_); f2(wf[7], q3.y, ff_);                          \
} while (0)

// ---------------- main fused kernel: 8 points per CTA, 512 threads ----------------
__global__ __launch_bounds__(TPB) void kpconv_kernel(
    const float* __restrict__ query,
    const float* __restrict__ support,
    const int*   __restrict__ nbr,
    const float* __restrict__ feat,
    const float* __restrict__ obias,
    const float* __restrict__ kpts,
    float*       __restrict__ out)
{
    extern __shared__ __align__(16) float sm[];
    float* s_u   = sm;                       // 8*1024 = 8192 floats (wf, aliased as red scratch)
    float* s_w   = sm + 8192;                // 8*34*20 = 5440 (weights 0..15, rowmax at [16])
    float* s_pts = s_w + 5440;               // 8*34*4 = 1088
    float* s_f0  = s_pts + 1088;             // 8*64 = 512
    float* s_dkp = s_f0 + 512;               // 8*15*4 = 480
    int*   s_idx = (int*)(s_dkp + 480);      // 8*34 = 272
    // total 15984 floats = 63936 B

    const int tid = threadIdx.x;
    const int p   = tid >> 6;      // point slot 0..7
    const int t   = tid & 63;      // channel / lane role
    const int n   = blockIdx.x * PPB + p;
    const int ib  = p * NN;

    // ===== Phase A: neighbor geometry + rigid influence weights =====
    if (t < NN) {
        float qx = query[n*3+0], qy = query[n*3+1], qz = query[n*3+2];
        int id = nbr[n*NN + t];
        s_idx[ib + t] = id;
        float px = support[id*3+0] - qx;
        float py = support[id*3+1] - qy;
        float pz = support[id*3+2] - qz;
        float* pr = &s_pts[(ib + t)*4];
        pr[0] = px; pr[1] = py; pr[2] = pz;
        float wl[16];
        float m = 0.f;
        #pragma unroll
        for (int k = 0; k < KP; k++) {
            float dx = px - kpts[k*3+0];
            float dy = py - kpts[k*3+1];
            float dz = pz - kpts[k*3+2];
            float sq = dx*dx + dy*dy + dz*dz;
            wl[k] = fmaxf(1.0f - 2.0f * sqrtf(sq), 0.0f);
            m = fmaxf(m, wl[k]);
        }
        wl[15] = 0.0f;
        float* wr = &s_w[(ib + t)*20];
        #pragma unroll
        for (int j = 0; j < 4; j++)
            *(float4*)&wr[j*4] = make_float4(wl[j*4+0], wl[j*4+1], wl[j*4+2], wl[j*4+3]);
        wr[16] = m;   // row-max flag for zero-row skip
    }
    __syncthreads();

    // ===== Phase B: wf0[k] = sum_a w0[a,k] * feat[a, c=t] =====
    {
        u64 wf[8];
        #pragma unroll
        for (int k = 0; k < 8; k++) wf[k] = 0ull;
        #pragma unroll 1
        for (int a0 = 0; a0 < NN; a0 += 2) {
            float fa = feat[s_idx[ib + a0    ] * INF + t];
            float fb = feat[s_idx[ib + a0 + 1] * INF + t];
            float m0 = s_w[(ib + a0    )*20 + 16];
            float m1 = s_w[(ib + a0 + 1)*20 + 16];
            if (m0 > 0.f) WROW_FMA(a0,     fa);
            if (m1 > 0.f) WROW_FMA(a0 + 1, fb);
        }
        #pragma unroll
        for (int kk = 0; kk < 8; kk++) {
            float2 v = unpack2(wf[kk]);
            s_u[p*1024 + (2*kk)*64 + t] = v.x;
            if (kk < 7) s_u[p*1024 + (2*kk+1)*64 + t] = v.y;
        }
    }
    __syncthreads();

    // ===== Phase C: f0[d] = bias[d] + sum_i wf0[i]*ow[i,d]; slot p covers 30 i4-blocks for ALL 8 points =====
    {
        u64 acc[PPB];
        #pragma unroll
        for (int pp = 0; pp < PPB; pp++) acc[pp] = 0ull;
        const int pbase = p * SLOT_I4;
        #pragma unroll 5
        for (int it = 0; it < SLOT_I4; it++) {
            int i4 = pbase + it;
            ulonglong2 w4 = *(const ulonglong2*)&g_owT[(i4 * 64 + t) * 4];
            #pragma unroll
            for (int pp = 0; pp < PPB; pp++) {
                ulonglong2 v4 = *(const ulonglong2*)&s_u[pp*1024 + i4*4];
                f2(acc[pp], v4.x, w4.x);
                f2(acc[pp], v4.y, w4.y);
            }
        }
        __syncthreads();   // all slots finished reading s_u (wf) -> safe to alias as red scratch
        #pragma unroll
        for (int pp = 0; pp < PPB; pp++) {
            float2 u = unpack2(acc[pp]);
            s_u[pp*1024 + p*64 + t] = u.x + u.y;
        }
    }
    __syncthreads();
    if (t < OFFD) {
        float f0 = obias[t];
        #pragma unroll
        for (int s = 0; s < PPB; s++) f0 += s_u[p*1024 + s*64 + t];
        s_f0[p*64 + t] = f0;
    }
    __syncthreads();

    // ===== offsets + modulations -> deformed kernel points =====
    if (t < KP) {
        float ox = s_f0[p*64 + 3*t+0] * EXTENTF;
        float oy = s_f0[p*64 + 3*t+1] * EXTENTF;
        float oz = s_f0[p*64 + 3*t+2] * EXTENTF;
        float* dk = &s_dkp[(p*KP + t)*4];
        dk[0] = kpts[t*3+0] + ox;
        dk[1] = kpts[t*3+1] + oy;
        dk[2] = kpts[t*3+2] + oz;
        dk[3] = 2.0f / (1.0f + expf(-s_f0[p*64 + 45 + t]));   // modulation
    }
    __syncthreads();

    // ===== Phase A2: deformed influence weights =====
    if (t < NN) {
        const float* pr = &s_pts[(ib + t)*4];
        float px = pr[0], py = pr[1], pz = pr[2];
        float wl[16];
        float m = 0.f;
        #pragma unroll
        for (int k = 0; k < KP; k++) {
            const float* dk = &s_dkp[(p*KP + k)*4];
            float dx = px - dk[0];
            float dy = py - dk[1];
            float dz = pz - dk[2];
            float sq = dx*dx + dy*dy + dz*dz;
            wl[k] = fmaxf(1.0f - 2.0f * sqrtf(sq), 0.0f);
            m = fmaxf(m, wl[k]);
        }
        wl[15] = 0.0f;
        float* wr = &s_w[(ib + t)*20];
        #pragma unroll
        for (int j = 0; j < 4; j++)
            *(float4*)&wr[j*4] = make_float4(wl[j*4+0], wl[j*4+1], wl[j*4+2], wl[j*4+3]);
        wr[16] = m;
    }
    __syncthreads();

    // ===== Phase D: wf[k] = mod[k] * sum_a w[a,k] * feat[a, c=t] =====
    {
        u64 wf[8];
        #pragma unroll
        for (int k = 0; k < 8; k++) wf[k] = 0ull;
        #pragma unroll 1
        for (int a0 = 0; a0 < NN; a0 += 2) {
            float fa = feat[s_idx[ib + a0    ] * INF + t];
            float fb = feat[s_idx[ib + a0 + 1] * INF + t];
            float m0 = s_w[(ib + a0    )*20 + 16];
            float m1 = s_w[(ib + a0 + 1)*20 + 16];
            if (m0 > 0.f) WROW_FMA(a0,     fa);
            if (m1 > 0.f) WROW_FMA(a0 + 1, fb);
        }
        #pragma unroll
        for (int kk = 0; kk < 8; kk++) {
            float2 v = unpack2(wf[kk]);
            int k0 = 2*kk;
            s_u[p*1024 + k0*64 + t] = v.x * s_dkp[(p*KP + k0)*4 + 3];
            if (kk < 7) s_u[p*1024 + (k0+1)*64 + t] = v.y * s_dkp[(p*KP + k0+1)*4 + 3];
        }
    }
    __syncthreads();

    // ===== Phase E: x[o] = sum_i wf[i] * weight[i,o] =====
    {
        u64 acc[PPB];
        #pragma unroll
        for (int pp = 0; pp < PPB; pp++) acc[pp] = 0ull;
        const int pbase = p * SLOT_I4;
        #pragma unroll 5
        for (int it = 0; it < SLOT_I4; it++) {
            int i4 = pbase + it;
            ulonglong2 w4 = *(const ulonglong2*)&g_wT[(i4 * 64 + t) * 4];
            #pragma unroll
            for (int pp = 0; pp < PPB; pp++) {
                ulonglong2 v4 = *(const ulonglong2*)&s_u[pp*1024 + i4*4];
                f2(acc[pp], v4.x, w4.x);
                f2(acc[pp], v4.y, w4.y);
            }
        }
        __syncthreads();
        #pragma unroll
        for (int pp = 0; pp < PPB; pp++) {
            float2 u = unpack2(acc[pp]);
            s_u[pp*1024 + p*64 + t] = u.x + u.y;
        }
    }
    __syncthreads();
    {
        float x = 0.f;
        #pragma unroll
        for (int s = 0; s < PPB; s++) x += s_u[p*1024 + s*64 + t];
        out[n * OUTF + t] = x;
        s_f0[p*64 + t] = x;                 // reuse as x buffer for BN partials
    }
    __syncthreads();
    if (tid < OUTF) {
        float s = 0.f, s2 = 0.f;
        #pragma unroll
        for (int pp = 0; pp < PPB; pp++) {
            float v = s_f0[pp*64 + tid];
            s += v; s2 += v * v;
        }
        g_psum  [blockIdx.x * OUTF + tid] = s;
        g_psumsq[blockIdx.x * OUTF + tid] = s2;
    }
}

// ---------------- BN stats: one block per channel (deterministic fixed-order reduce) ----------------
__global__ void stats_kernel(const float* __restrict__ gamma, const float* __restrict__ beta) {
    int o = blockIdx.x;
    int tid = threadIdx.x;
    float s = 0.f, s2 = 0.f;
    for (int j = tid; j < NBLK; j += blockDim.x) {
        s  += g_psum  [j * OUTF + o];
        s2 += g_psumsq[j * OUTF + o];
    }
    __shared__ float sh[256], sh2[256];
    sh[tid] = s; sh2[tid] = s2;
    __syncthreads();
    for (int st = 128; st > 0; st >>= 1) {
        if (tid < st) { sh[tid] += sh[tid + st]; sh2[tid] += sh2[tid + st]; }
        __syncthreads();
    }
    if (tid == 0) {
        float mean = sh[0]  / (float)NPTS;
        float var  = sh2[0] / (float)NPTS - mean * mean;
        float sc   = rsqrtf(var + 1e-6f) * gamma[o];
        g_scale[o] = sc;
        g_shift[o] = beta[o] - mean * sc;
    }
}

// ---------------- BN apply + LeakyReLU ----------------
__global__ void bn_kernel(float* __restrict__ out) {
    const int total4 = NPTS * OUTF / 4;
    for (int i = blockIdx.x * blockDim.x + threadIdx.x; i < total4; i += gridDim.x * blockDim.x) {
        float4 v = ((float4*)out)[i];
        int ch = (i & 15) * 4;
        float4 sc = *(const float4*)&g_scale[ch];
        float4 sh = *(const float4*)&g_shift[ch];
        v.x = v.x * sc.x + sh.x;  v.x = v.x >= 0.f ? v.x : 0.1f * v.x;
        v.y = v.y * sc.y + sh.y;  v.y = v.y >= 0.f ? v.y : 0.1f * v.y;
        v.z = v.z * sc.z + sh.z;  v.z = v.z >= 0.f ? v.z : 0.1f * v.z;
        v.w = v.w * sc.w + sh.w;  v.w = v.w >= 0.f ? v.w : 0.1f * v.w;
        ((float4*)out)[i] = v;
    }
}

// ---------------- launch ----------------
extern "C" void kernel_launch(void* const* d_in, const int* in_sizes, int n_in,
                              void* d_out, int out_size) {
    const float* query   = (const float*)d_in[0];
    const float* support = (const float*)d_in[1];
    const int*   nbr     = (const int*)  d_in[2];
    const float* feat    = (const float*)d_in[3];
    const float* weight  = (const float*)d_in[4];
    const float* ow      = (const float*)d_in[5];
    const float* obias   = (const float*)d_in[6];
    const float* gamma   = (const float*)d_in[7];
    const float* beta    = (const float*)d_in[8];
    const float* kpts    = (const float*)d_in[9];
    float* out = (float*)d_out;

    const int smem_bytes = 15984 * 4;  // 63,936 B
    static int attr_set = 0;
    if (!attr_set) {
        cudaFuncSetAttribute(kpconv_kernel, cudaFuncAttributeMaxDynamicSharedMemorySize, smem_bytes);
        attr_set = 1;
    }

    prep_kernel<<<120, 512>>>(ow, weight);
    kpconv_kernel<<<NBLK, TPB, smem_bytes>>>(query, support, nbr, feat, obias, kpts, out);
    stats_kernel<<<OUTF, 256>>>(gamma, beta);
    bn_kernel<<<2048, 256>>>(out);
}

// round 10
// speedup vs baseline: 1.1241x; 1.1241x over previous
#include <cuda_runtime.h>
#include <cuda_bf16.h>
#include <math.h>
#include <stdint.h>

#define NPTS   65536
#define NN     34
#define KP     15
#define INF    64
#define OUTF   64
#define EXTENTF 0.5f
#define PPB    4
#define TPB    256
#define NBLK_G (NPTS / PPB)       // 16384 gather CTAs
#define KDIM   960
#define KW     480                // u32 words per A/B row (bf16 pairs)
#define MT     128                // GEMM tile M
#define NGEMM  (NPTS / MT)        // 512 GEMM CTAs
#define NCHUNK 15

// GEMM smem: padded tiles, row stride 144B (72 bf16) -> conflict-free ldmatrix
#define AS      144
#define OFS_A1  0
#define OFS_A2  18432
#define OFS_B1  36864
#define OFS_B2  46080
#define SM_GEMM 55296

typedef unsigned long long u64;
typedef unsigned int u32;

// ---------------- device scratch ----------------
__device__ __align__(16) u32 g_A1[NPTS * KW];     // wf hi  (bf16 pairs)
__device__ __align__(16) u32 g_A2[NPTS * KW];     // wf residual
__device__ __align__(16) u32 g_OB1[64 * KW];      // offset_weight^T hi [d][i] pairs
__device__ __align__(16) u32 g_OB2[64 * KW];
__device__ __align__(16) u32 g_WB1[64 * KW];      // weight^T hi [o][i] pairs
__device__ __align__(16) u32 g_WB2[64 * KW];
__device__ __align__(16) float g_dkp[NPTS * KP * 4];  // deformed kp xyz + modulation
__device__ float g_psum  [NGEMM * OUTF];
__device__ float g_psumsq[NGEMM * OUTF];
__device__ __align__(16) float g_scale[OUTF];
__device__ __align__(16) float g_shift[OUTF];

// ---------------- helpers ----------------
__device__ __forceinline__ void f2fma(float2 &acc, float2 a, float2 b) {
    asm("{\n\t"
        ".reg .b64 ra, rb, rc;\n\t"
        "mov.b64 ra, {%2, %3};\n\t"
        "mov.b64 rb, {%4, %5};\n\t"
        "mov.b64 rc, {%0, %1};\n\t"
        "fma.rn.f32x2 rc, ra, rb, rc;\n\t"
        "mov.b64 {%0, %1}, rc;\n\t"
        "}"
        : "+f"(acc.x), "+f"(acc.y)
        : "f"(a.x), "f"(a.y), "f"(b.x), "f"(b.y));
}

__device__ __forceinline__ uint32_t smem_u32(const void* p) {
    uint32_t a;
    asm("{ .reg .u64 t; cvta.to.shared.u64 t, %1; cvt.u32.u64 %0, t; }" : "=r"(a) : "l"(p));
    return a;
}

#define LDSM_X4(r, addr)                                                          \
    asm volatile("ldmatrix.sync.aligned.m8n8.x4.shared.b16 {%0,%1,%2,%3}, [%4];"  \
        : "=r"((r)[0]), "=r"((r)[1]), "=r"((r)[2]), "=r"((r)[3]) : "r"(addr))

#define MMA_BF16(d, a, b0, b1)                                                    \
    asm volatile("mma.sync.aligned.m16n8k16.row.col.f32.bf16.bf16.f32 "           \
        "{%0,%1,%2,%3}, {%4,%5,%6,%7}, {%8,%9}, {%0,%1,%2,%3};"                   \
        : "+f"((d)[0]), "+f"((d)[1]), "+f"((d)[2]), "+f"((d)[3])                  \
        : "r"((a)[0]), "r"((a)[1]), "r"((a)[2]), "r"((a)[3]), "r"(b0), "r"(b1))

__device__ __forceinline__ u32 pack_bf16(float lo, float hi) {
    __nv_bfloat162 h = __floats2bfloat162_rn(lo, hi);
    return *(u32*)&h;
}
__device__ __forceinline__ float bf16_res(float v) {
    return v - __bfloat162float(__float2bfloat16_rn(v));
}

// ---------------- prep: hi/lo bf16 transposed weight matrices ----------------
__global__ void prep_kernel(const float* __restrict__ ow, const float* __restrict__ w) {
    int t = blockIdx.x * blockDim.x + threadIdx.x;
    int stride = gridDim.x * blockDim.x;
    for (int idx = t; idx < 64 * KW; idx += stride) {
        int d = idx / KW, j = idx - d * KW;
        float v0 = (d < 60) ? ow[(2 * j) * 60 + d] : 0.f;
        float v1 = (d < 60) ? ow[(2 * j + 1) * 60 + d] : 0.f;
        g_OB1[idx] = pack_bf16(v0, v1);
        g_OB2[idx] = pack_bf16(bf16_res(v0), bf16_res(v1));
    }
    for (int idx = t; idx < 64 * KW; idx += stride) {
        int o = idx / KW, j = idx - o * KW;
        float v0 = w[(2 * j) * 64 + o];
        float v1 = w[(2 * j + 1) * 64 + o];
        g_WB1[idx] = pack_bf16(v0, v1);
        g_WB2[idx] = pack_bf16(bf16_res(v0), bf16_res(v1));
    }
}

// ---------------- gather phase common ----------------
#define GATHER_PHASE(OUT_EXPR) do {                                              \
    float2 wf[8];                                                                \
    _Pragma("unroll")                                                            \
    for (int k = 0; k < 8; k++) wf[k] = make_float2(0.f, 0.f);                   \
    _Pragma("unroll 2")                                                          \
    for (int a = 0; a < NN; a++) {                                               \
        float f = feat[s_idx[p][a] * INF + t];                                   \
        float2 ff = make_float2(f, f);                                           \
        const float4* wr = (const float4*)&s_w[p][a][0];                         \
        float4 w0 = wr[0], w1 = wr[1], w2 = wr[2], w3 = wr[3];                   \
        f2fma(wf[0], make_float2(w0.x, w0.y), ff);                               \
        f2fma(wf[1], make_float2(w0.z, w0.w), ff);                               \
        f2fma(wf[2], make_float2(w1.x, w1.y), ff);                               \
        f2fma(wf[3], make_float2(w1.z, w1.w), ff);                               \
        f2fma(wf[4], make_float2(w2.x, w2.y), ff);                               \
        f2fma(wf[5], make_float2(w2.z, w2.w), ff);                               \
        f2fma(wf[6], make_float2(w3.x, w3.y), ff);                               \
        f2fma(wf[7], make_float2(w3.z, w3.w), ff);                               \
    }                                                                            \
    _Pragma("unroll")                                                            \
    for (int k = 0; k < KP; k++) {                                               \
        float v = (k & 1) ? wf[k >> 1].y : wf[k >> 1].x;                         \
        OUT_EXPR;                                                                \
    }                                                                            \
} while (0)

#define CONVERT_STORE() do {                                                     \
    for (int idx = tid; idx < PPB * KW; idx += TPB) {                            \
        int pp = idx / KW, j = idx - pp * KW;                                    \
        float v0 = s_wf[pp][2 * j], v1 = s_wf[pp][2 * j + 1];                    \
        g_A1[(n0 + pp) * KW + j] = pack_bf16(v0, v1);                            \
        g_A2[(n0 + pp) * KW + j] = pack_bf16(bf16_res(v0), bf16_res(v1));        \
    }                                                                            \
} while (0)

// ---------------- gather 1: rigid weights -> wf0 ----------------
__global__ __launch_bounds__(TPB) void gather1_kernel(
    const float* __restrict__ query, const float* __restrict__ support,
    const int* __restrict__ nbr, const float* __restrict__ feat,
    const float* __restrict__ kpts)
{
    __shared__ __align__(16) float s_w [PPB][NN][20];
    __shared__ int                 s_idx[PPB][NN];
    __shared__ __align__(16) float s_wf[PPB][KDIM];

    const int tid = threadIdx.x;
    const int p   = tid >> 6;
    const int t   = tid & 63;
    const int n0  = blockIdx.x * PPB;
    const int n   = n0 + p;

    if (t < NN) {
        float qx = query[n*3+0], qy = query[n*3+1], qz = query[n*3+2];
        int id = nbr[n*NN + t];
        s_idx[p][t] = id;
        float px = support[id*3+0] - qx;
        float py = support[id*3+1] - qy;
        float pz = support[id*3+2] - qz;
        float wl[16];
        #pragma unroll
        for (int k = 0; k < KP; k++) {
            float dx = px - kpts[k*3+0];
            float dy = py - kpts[k*3+1];
            float dz = pz - kpts[k*3+2];
            float sq = dx*dx + dy*dy + dz*dz;
            wl[k] = fmaxf(1.0f - 2.0f * sqrtf(sq), 0.0f);
        }
        wl[15] = 0.0f;
        #pragma unroll
        for (int j = 0; j < 4; j++)
            *(float4*)&s_w[p][t][j*4] = make_float4(wl[j*4+0], wl[j*4+1], wl[j*4+2], wl[j*4+3]);
    }
    __syncthreads();

    GATHER_PHASE(s_wf[p][k * INF + t] = v);
    __syncthreads();
    CONVERT_STORE();
}

// ---------------- gather 2: deformed weights (+mod) -> wf ----------------
__global__ __launch_bounds__(TPB) void gather2_kernel(
    const float* __restrict__ query, const float* __restrict__ support,
    const int* __restrict__ nbr, const float* __restrict__ feat)
{
    __shared__ __align__(16) float s_w [PPB][NN][20];
    __shared__ int                 s_idx[PPB][NN];
    __shared__ __align__(16) float s_wf[PPB][KDIM];
    __shared__ __align__(16) float s_dkp[PPB][KP][4];

    const int tid = threadIdx.x;
    const int p   = tid >> 6;
    const int t   = tid & 63;
    const int n0  = blockIdx.x * PPB;
    const int n   = n0 + p;

    if (t < KP) {
        float4 dk = ((const float4*)g_dkp)[n * KP + t];
        *(float4*)&s_dkp[p][t][0] = dk;
    }
    __syncthreads();

    if (t < NN) {
        float qx = query[n*3+0], qy = query[n*3+1], qz = query[n*3+2];
        int id = nbr[n*NN + t];
        s_idx[p][t] = id;
        float px = support[id*3+0] - qx;
        float py = support[id*3+1] - qy;
        float pz = support[id*3+2] - qz;
        float wl[16];
        #pragma unroll
        for (int k = 0; k < KP; k++) {
            float dx = px - s_dkp[p][k][0];
            float dy = py - s_dkp[p][k][1];
            float dz = pz - s_dkp[p][k][2];
            float sq = dx*dx + dy*dy + dz*dz;
            wl[k] = fmaxf(1.0f - 2.0f * sqrtf(sq), 0.0f);
        }
        wl[15] = 0.0f;
        #pragma unroll
        for (int j = 0; j < 4; j++)
            *(float4*)&s_w[p][t][j*4] = make_float4(wl[j*4+0], wl[j*4+1], wl[j*4+2], wl[j*4+3]);
    }
    __syncthreads();

    GATHER_PHASE(s_wf[p][k * INF + t] = v * s_dkp[p][k][3]);
    __syncthreads();
    CONVERT_STORE();
}

// ---------------- warp-MMA GEMM mainloop ----------------
// D[128 x 64] = A[128 x 960] * B[64 x 960]^T, bf16 3-product split.
// 8 warps; warp w owns M rows [16w,16w+16). Result left in acc[32] (8 nblocks x 4).
__device__ __forceinline__ void run_gemm_wm(const u32* __restrict__ B1g,
                                            const u32* __restrict__ B2g,
                                            char* smem, float* acc) {
    const int tid  = threadIdx.x;
    const int wid  = tid >> 5;
    const int lane = tid & 31;
    const int pt0  = blockIdx.x * MT;

    char* sA1 = smem + OFS_A1;
    char* sA2 = smem + OFS_A2;
    char* sB1 = smem + OFS_B1;
    char* sB2 = smem + OFS_B2;
    const uint32_t a1b = smem_u32(sA1), a2b = smem_u32(sA2);
    const uint32_t b1b = smem_u32(sB1), b2b = smem_u32(sB2);

    // ldmatrix lane-address components
    const uint32_t aoff = (uint32_t)(wid * 16 + (lane & 15)) * AS + ((lane >> 4) << 4);
    const uint32_t brow = (uint32_t)(((lane >> 4) << 3) + (lane & 7));
    const uint32_t boff = brow * AS + (((lane >> 3) & 1) << 4);

    #pragma unroll
    for (int i = 0; i < 32; i++) acc[i] = 0.f;

    #pragma unroll 1
    for (int c = 0; c < NCHUNK; c++) {
        // stage tiles: A rows 128x128B, B rows 64x128B (hi+lo each)
        for (int u = tid; u < 1024; u += 256) {
            int r = u >> 3, q = u & 7;
            const u32* s1 = g_A1 + (pt0 + r) * KW + c * 32 + q * 4;
            const u32* s2 = g_A2 + (pt0 + r) * KW + c * 32 + q * 4;
            *(uint4*)(sA1 + r * AS + q * 16) = *(const uint4*)s1;
            *(uint4*)(sA2 + r * AS + q * 16) = *(const uint4*)s2;
        }
        for (int u = tid; u < 512; u += 256) {
            int r = u >> 3, q = u & 7;
            *(uint4*)(sB1 + r * AS + q * 16) = *(const uint4*)(B1g + r * KW + c * 32 + q * 4);
            *(uint4*)(sB2 + r * AS + q * 16) = *(const uint4*)(B2g + r * KW + c * 32 + q * 4);
        }
        __syncthreads();

        #pragma unroll
        for (int ks = 0; ks < 4; ks++) {
            const uint32_t kb = (uint32_t)(ks * 32);
            uint32_t a1[4], a2[4];
            LDSM_X4(a1, a1b + aoff + kb);
            LDSM_X4(a2, a2b + aoff + kb);
            #pragma unroll
            for (int nb2 = 0; nb2 < 4; nb2++) {
                uint32_t b1[4], b2[4];
                uint32_t bo = (uint32_t)(nb2 * 16) * AS + boff + kb;
                LDSM_X4(b1, b1b + bo);
                LDSM_X4(b2, b2b + bo);
                float* d0 = acc + (nb2 * 2) * 4;
                float* d1 = acc + (nb2 * 2 + 1) * 4;
                MMA_BF16(d0, a1, b1[0], b1[1]);
                MMA_BF16(d1, a1, b1[2], b1[3]);
                MMA_BF16(d0, a1, b2[0], b2[1]);
                MMA_BF16(d1, a1, b2[2], b2[3]);
                MMA_BF16(d0, a2, b1[0], b1[1]);
                MMA_BF16(d1, a2, b1[2], b1[3]);
            }
        }
        __syncthreads();
    }
}

// store acc -> sx[128][68] staging (in smem, overlays tile region)
__device__ __forceinline__ void acc_to_smem(float* sx, const float* acc) {
    const int tid  = threadIdx.x;
    const int wid  = tid >> 5;
    const int lane = tid & 31;
    int r0 = wid * 16 + (lane >> 2);
    int cb = (lane & 3) * 2;
    #pragma unroll
    for (int nb = 0; nb < 8; nb++) {
        int col = nb * 8 + cb;
        sx[r0 * 68 + col]       = acc[nb * 4 + 0];
        sx[r0 * 68 + col + 1]   = acc[nb * 4 + 1];
        sx[(r0 + 8) * 68 + col]     = acc[nb * 4 + 2];
        sx[(r0 + 8) * 68 + col + 1] = acc[nb * 4 + 3];
    }
}

// ---------------- GEMM 1: f0 -> deformed kernel points + modulations ----------------
__global__ __launch_bounds__(256, 1) void gemm1_kernel(
    const float* __restrict__ obias, const float* __restrict__ kpts) {
    extern __shared__ __align__(16) char smem[];
    float acc[32];
    run_gemm_wm(g_OB1, g_OB2, smem, acc);

    float* sx = (float*)smem;   // 128*68*4 = 34816 B, tiles dead now
    acc_to_smem(sx, acc);
    __syncthreads();

    const int tid = threadIdx.x;
    if (tid < MT) {
        int n = blockIdx.x * MT + tid;
        float f0[60];
        #pragma unroll
        for (int i = 0; i < 60; i++) f0[i] = sx[tid * 68 + i] + obias[i];
        #pragma unroll
        for (int k = 0; k < KP; k++) {
            float4 o;
            o.x = kpts[k*3+0] + f0[3*k+0] * EXTENTF;
            o.y = kpts[k*3+1] + f0[3*k+1] * EXTENTF;
            o.z = kpts[k*3+2] + f0[3*k+2] * EXTENTF;
            o.w = 2.0f / (1.0f + expf(-f0[45 + k]));
            ((float4*)g_dkp)[n * KP + k] = o;
        }
    }
}

// ---------------- GEMM 2: x -> out + BN partials ----------------
__global__ __launch_bounds__(256, 1) void gemm2_kernel(float* __restrict__ out) {
    extern __shared__ __align__(16) char smem[];
    float acc[32];
    run_gemm_wm(g_WB1, g_WB2, smem, acc);

    float* sx = (float*)smem;
    acc_to_smem(sx, acc);
    __syncthreads();

    const int tid = threadIdx.x;
    {
        const int base4 = blockIdx.x * MT * OUTF / 4;
        for (int v = tid; v < MT * OUTF / 4; v += 256) {
            int pl = v >> 4, j = v & 15;
            float4 val = *(float4*)&sx[pl * 68 + j * 4];
            ((float4*)out)[base4 + v] = val;
        }
    }
    if (tid < OUTF) {
        float s = 0.f, s2 = 0.f;
        for (int pl = 0; pl < MT; pl++) {
            float v = sx[pl * 68 + tid];
            s += v; s2 += v * v;
        }
        g_psum  [blockIdx.x * OUTF + tid] = s;
        g_psumsq[blockIdx.x * OUTF + tid] = s2;
    }
}

// ---------------- BN stats ----------------
__global__ void stats_kernel(const float* __restrict__ gamma, const float* __restrict__ beta) {
    int o = blockIdx.x;
    int tid = threadIdx.x;
    float s = 0.f, s2 = 0.f;
    for (int j = tid; j < NGEMM; j += blockDim.x) {
        s  += g_psum  [j * OUTF + o];
        s2 += g_psumsq[j * OUTF + o];
    }
    __shared__ float sh[256], sh2[256];
    sh[tid] = s; sh2[tid] = s2;
    __syncthreads();
    for (int st = 128; st > 0; st >>= 1) {
        if (tid < st) { sh[tid] += sh[tid + st]; sh2[tid] += sh2[tid + st]; }
        __syncthreads();
    }
    if (tid == 0) {
        float mean = sh[0]  / (float)NPTS;
        float var  = sh2[0] / (float)NPTS - mean * mean;
        float sc   = rsqrtf(var + 1e-6f) * gamma[o];
        g_scale[o] = sc;
        g_shift[o] = beta[o] - mean * sc;
    }
}

// ---------------- BN apply + LeakyReLU ----------------
__global__ void bn_kernel(float* __restrict__ out) {
    const int total4 = NPTS * OUTF / 4;
    for (int i = blockIdx.x * blockDim.x + threadIdx.x; i < total4; i += gridDim.x * blockDim.x) {
        float4 v = ((float4*)out)[i];
        int ch = (i & 15) * 4;
        float4 sc = *(const float4*)&g_scale[ch];
        float4 sh = *(const float4*)&g_shift[ch];
        v.x = v.x * sc.x + sh.x;  v.x = v.x >= 0.f ? v.x : 0.1f * v.x;
        v.y = v.y * sc.y + sh.y;  v.y = v.y >= 0.f ? v.y : 0.1f * v.y;
        v.z = v.z * sc.z + sh.z;  v.z = v.z >= 0.f ? v.z : 0.1f * v.z;
        v.w = v.w * sc.w + sh.w;  v.w = v.w >= 0.f ? v.w : 0.1f * v.w;
        ((float4*)out)[i] = v;
    }
}

// ---------------- launch ----------------
extern "C" void kernel_launch(void* const* d_in, const int* in_sizes, int n_in,
                              void* d_out, int out_size) {
    const float* query   = (const float*)d_in[0];
    const float* support = (const float*)d_in[1];
    const int*   nbr     = (const int*)  d_in[2];
    const float* feat    = (const float*)d_in[3];
    const float* weight  = (const float*)d_in[4];
    const float* ow      = (const float*)d_in[5];
    const float* obias   = (const float*)d_in[6];
    const float* gamma   = (const float*)d_in[7];
    const float* beta    = (const float*)d_in[8];
    const float* kpts    = (const float*)d_in[9];
    float* out = (float*)d_out;

    static int attr_set = 0;
    if (!attr_set) {
        cudaFuncSetAttribute(gemm1_kernel, cudaFuncAttributeMaxDynamicSharedMemorySize, SM_GEMM);
        cudaFuncSetAttribute(gemm2_kernel, cudaFuncAttributeMaxDynamicSharedMemorySize, SM_GEMM);
        attr_set = 1;
    }

    prep_kernel   <<<64, 256>>>(ow, weight);
    gather1_kernel<<<NBLK_G, TPB>>>(query, support, nbr, feat, kpts);
    gemm1_kernel  <<<NGEMM, 256, SM_GEMM>>>(obias, kpts);
    gather2_kernel<<<NBLK_G, TPB>>>(query, support, nbr, feat);
    gemm2_kernel  <<<NGEMM, 256, SM_GEMM>>>(out);
    stats_kernel  <<<OUTF, 256>>>(gamma, beta);
    bn_kernel     <<<2048, 256>>>(out);
}

// round 11
// speedup vs baseline: 1.6439x; 1.4624x over previous
#include <cuda_runtime.h>
#include <cuda_bf16.h>
#include <math.h>
#include <stdint.h>

#define NPTS   65536
#define NN     34
#define KP     15
#define INF    64
#define OUTF   64
#define EXTENTF 0.5f
#define PPB    8                  // points per gather CTA (1 warp each)
#define TPB    256
#define NBLK_G (NPTS / PPB)       // 8192 gather CTAs
#define KW2    512                // u32 words per A/B row (bf16 pairs), K'=1024 (i' = c*16+k, k=15 pad)
#define MT     128                // GEMM tile M
#define NGEMM  (NPTS / MT)        // 512 GEMM CTAs
#define NCHUNK 16                 // 1024 / 64

// GEMM smem: padded tiles, row stride 144B (72 bf16) -> conflict-free ldmatrix
#define AS      144
#define OFS_A1  0
#define OFS_A2  18432
#define OFS_B1  36864
#define OFS_B2  46080
#define SM_GEMM 55296

typedef unsigned long long u64;
typedef unsigned int u32;

// ---------------- device scratch ----------------
__device__ __align__(16) u32 g_A1[NPTS * KW2];    // wf hi  (bf16 pairs, i' = c*16+k)
__device__ __align__(16) u32 g_A2[NPTS * KW2];    // wf residual
__device__ __align__(16) u32 g_OB1[64 * KW2];     // offset_weight^T hi [d][i'] pairs
__device__ __align__(16) u32 g_OB2[64 * KW2];
__device__ __align__(16) u32 g_WB1[64 * KW2];     // weight^T hi [o][i'] pairs
__device__ __align__(16) u32 g_WB2[64 * KW2];
__device__ __align__(16) float g_dkp[NPTS * KP * 4];  // deformed kp xyz + modulation
__device__ float g_psum  [NGEMM * OUTF];
__device__ float g_psumsq[NGEMM * OUTF];
__device__ __align__(16) float g_scale[OUTF];
__device__ __align__(16) float g_shift[OUTF];

// ---------------- helpers ----------------
__device__ __forceinline__ void f2fma(float2 &acc, float2 a, float2 b) {
    asm("{\n\t"
        ".reg .b64 ra, rb, rc;\n\t"
        "mov.b64 ra, {%2, %3};\n\t"
        "mov.b64 rb, {%4, %5};\n\t"
        "mov.b64 rc, {%0, %1};\n\t"
        "fma.rn.f32x2 rc, ra, rb, rc;\n\t"
        "mov.b64 {%0, %1}, rc;\n\t"
        "}"
        : "+f"(acc.x), "+f"(acc.y)
        : "f"(a.x), "f"(a.y), "f"(b.x), "f"(b.y));
}

__device__ __forceinline__ uint32_t smem_u32(const void* p) {
    uint32_t a;
    asm("{ .reg .u64 t; cvta.to.shared.u64 t, %1; cvt.u32.u64 %0, t; }" : "=r"(a) : "l"(p));
    return a;
}

#define LDSM_X4(r, addr)                                                          \
    asm volatile("ldmatrix.sync.aligned.m8n8.x4.shared.b16 {%0,%1,%2,%3}, [%4];"  \
        : "=r"((r)[0]), "=r"((r)[1]), "=r"((r)[2]), "=r"((r)[3]) : "r"(addr))

#define MMA_BF16(d, a, b0, b1)                                                    \
    asm volatile("mma.sync.aligned.m16n8k16.row.col.f32.bf16.bf16.f32 "           \
        "{%0,%1,%2,%3}, {%4,%5,%6,%7}, {%8,%9}, {%0,%1,%2,%3};"                   \
        : "+f"((d)[0]), "+f"((d)[1]), "+f"((d)[2]), "+f"((d)[3])                  \
        : "r"((a)[0]), "r"((a)[1]), "r"((a)[2]), "r"((a)[3]), "r"(b0), "r"(b1))

__device__ __forceinline__ u32 pack_bf16(float lo, float hi) {
    __nv_bfloat162 h = __floats2bfloat162_rn(lo, hi);
    return *(u32*)&h;
}
__device__ __forceinline__ float bf16_res(float v) {
    return v - __bfloat162float(__float2bfloat16_rn(v));
}

// ---------------- prep: hi/lo bf16 transposed weight matrices, i' = c*16+k order ----------------
__global__ void prep_kernel(const float* __restrict__ ow, const float* __restrict__ w) {
    int t = blockIdx.x * blockDim.x + threadIdx.x;
    int stride = gridDim.x * blockDim.x;
    for (int idx = t; idx < 64 * KW2; idx += stride) {
        int row = idx / KW2, j = idx - row * KW2;
        int ip0 = 2 * j, ip1 = 2 * j + 1;
        int c0 = ip0 >> 4, k0 = ip0 & 15;
        int c1 = ip1 >> 4, k1 = ip1 & 15;
        // offset_weight [i=k*64+c][d=60]
        float v0 = (k0 < 15 && row < 60) ? ow[(k0 * 64 + c0) * 60 + row] : 0.f;
        float v1 = (k1 < 15 && row < 60) ? ow[(k1 * 64 + c1) * 60 + row] : 0.f;
        g_OB1[idx] = pack_bf16(v0, v1);
        g_OB2[idx] = pack_bf16(bf16_res(v0), bf16_res(v1));
        // weight [i=k*64+c][o=64]
        float u0 = (k0 < 15) ? w[(k0 * 64 + c0) * 64 + row] : 0.f;
        float u1 = (k1 < 15) ? w[(k1 * 64 + c1) * 64 + row] : 0.f;
        g_WB1[idx] = pack_bf16(u0, u1);
        g_WB2[idx] = pack_bf16(bf16_res(u0), bf16_res(u1));
    }
}

// ---------------- gather inner loop: warp per point, 2 channels per lane ----------------
// acc[j][h]: j = k-pair (k=2j, 2j+1), h = channel half (c = lane + 32h)
#define GATHER_LOOP() do {                                                       \
    _Pragma("unroll 2")                                                          \
    for (int a = 0; a < NN; a++) {                                               \
        int id = s_idx[p][a];                                                    \
        float f0 = feat[id * INF + lane];                                        \
        float f1 = feat[id * INF + 32 + lane];                                   \
        float2 ff0 = make_float2(f0, f0);                                        \
        float2 ff1 = make_float2(f1, f1);                                        \
        const float4* wr = (const float4*)&s_w[p][a][0];                         \
        float4 w0 = wr[0], w1 = wr[1], w2 = wr[2], w3 = wr[3];                   \
        f2fma(acc[0][0], make_float2(w0.x, w0.y), ff0);                          \
        f2fma(acc[0][1], make_float2(w0.x, w0.y), ff1);                          \
        f2fma(acc[1][0], make_float2(w0.z, w0.w), ff0);                          \
        f2fma(acc[1][1], make_float2(w0.z, w0.w), ff1);                          \
        f2fma(acc[2][0], make_float2(w1.x, w1.y), ff0);                          \
        f2fma(acc[2][1], make_float2(w1.x, w1.y), ff1);                          \
        f2fma(acc[3][0], make_float2(w1.z, w1.w), ff0);                          \
        f2fma(acc[3][1], make_float2(w1.z, w1.w), ff1);                          \
        f2fma(acc[4][0], make_float2(w2.x, w2.y), ff0);                          \
        f2fma(acc[4][1], make_float2(w2.x, w2.y), ff1);                          \
        f2fma(acc[5][0], make_float2(w2.z, w2.w), ff0);                          \
        f2fma(acc[5][1], make_float2(w2.z, w2.w), ff1);                          \
        f2fma(acc[6][0], make_float2(w3.x, w3.y), ff0);                          \
        f2fma(acc[6][1], make_float2(w3.x, w3.y), ff1);                          \
        f2fma(acc[7][0], make_float2(w3.z, w3.w), ff0);                          \
        f2fma(acc[7][1], make_float2(w3.z, w3.w), ff1);                          \
    }                                                                            \
} while (0)

// direct bf16 hi/res pack + store: lane writes 8 pairs per channel half
#define STORE_A(nn) do {                                                         \
    _Pragma("unroll")                                                            \
    for (int h = 0; h < 2; h++) {                                                \
        int c = lane + h * 32;                                                   \
        u32 base = (u32)(nn) * KW2 + (u32)c * 8;                                 \
        uint4 hi0, hi1, lo0, lo1;                                                \
        hi0.x = pack_bf16(acc[0][h].x, acc[0][h].y);                             \
        hi0.y = pack_bf16(acc[1][h].x, acc[1][h].y);                             \
        hi0.z = pack_bf16(acc[2][h].x, acc[2][h].y);                             \
        hi0.w = pack_bf16(acc[3][h].x, acc[3][h].y);                             \
        hi1.x = pack_bf16(acc[4][h].x, acc[4][h].y);                             \
        hi1.y = pack_bf16(acc[5][h].x, acc[5][h].y);                             \
        hi1.z = pack_bf16(acc[6][h].x, acc[6][h].y);                             \
        hi1.w = pack_bf16(acc[7][h].x, acc[7][h].y);                             \
        lo0.x = pack_bf16(bf16_res(acc[0][h].x), bf16_res(acc[0][h].y));         \
        lo0.y = pack_bf16(bf16_res(acc[1][h].x), bf16_res(acc[1][h].y));         \
        lo0.z = pack_bf16(bf16_res(acc[2][h].x), bf16_res(acc[2][h].y));         \
        lo0.w = pack_bf16(bf16_res(acc[3][h].x), bf16_res(acc[3][h].y));         \
        lo1.x = pack_bf16(bf16_res(acc[4][h].x), bf16_res(acc[4][h].y));         \
        lo1.y = pack_bf16(bf16_res(acc[5][h].x), bf16_res(acc[5][h].y));         \
        lo1.z = pack_bf16(bf16_res(acc[6][h].x), bf16_res(acc[6][h].y));         \
        lo1.w = pack_bf16(bf16_res(acc[7][h].x), bf16_res(acc[7][h].y));         \
        *(uint4*)&g_A1[base]     = hi0;                                          \
        *(uint4*)&g_A1[base + 4] = hi1;                                          \
        *(uint4*)&g_A2[base]     = lo0;                                          \
        *(uint4*)&g_A2[base + 4] = lo1;                                          \
    }                                                                            \
} while (0)

// ---------------- gather 1: rigid weights -> wf0 -> A (bf16 split) ----------------
__global__ __launch_bounds__(TPB) void gather1_kernel(
    const float* __restrict__ query, const float* __restrict__ support,
    const int* __restrict__ nbr, const float* __restrict__ feat,
    const float* __restrict__ kpts)
{
    __shared__ __align__(16) float s_w [PPB][NN][20];
    __shared__ int                 s_idx[PPB][NN];

    const int tid  = threadIdx.x;
    const int p    = tid >> 5;
    const int lane = tid & 31;
    const int n    = blockIdx.x * PPB + p;

    for (int a = lane; a < NN; a += 32) {
        float qx = query[n*3+0], qy = query[n*3+1], qz = query[n*3+2];
        int id = nbr[n*NN + a];
        s_idx[p][a] = id;
        float px = support[id*3+0] - qx;
        float py = support[id*3+1] - qy;
        float pz = support[id*3+2] - qz;
        float wl[16];
        #pragma unroll
        for (int k = 0; k < KP; k++) {
            float dx = px - kpts[k*3+0];
            float dy = py - kpts[k*3+1];
            float dz = pz - kpts[k*3+2];
            float sq = dx*dx + dy*dy + dz*dz;
            wl[k] = fmaxf(1.0f - 2.0f * sqrtf(sq), 0.0f);
        }
        wl[15] = 0.0f;
        #pragma unroll
        for (int j = 0; j < 4; j++)
            *(float4*)&s_w[p][a][j*4] = make_float4(wl[j*4+0], wl[j*4+1], wl[j*4+2], wl[j*4+3]);
    }
    __syncwarp();

    float2 acc[8][2];
    #pragma unroll
    for (int j = 0; j < 8; j++) { acc[j][0] = make_float2(0.f,0.f); acc[j][1] = make_float2(0.f,0.f); }

    GATHER_LOOP();
    STORE_A(n);
}

// ---------------- gather 2: deformed weights (+mod) -> wf -> A (bf16 split) ----------------
__global__ __launch_bounds__(TPB) void gather2_kernel(
    const float* __restrict__ query, const float* __restrict__ support,
    const int* __restrict__ nbr, const float* __restrict__ feat)
{
    __shared__ __align__(16) float s_w  [PPB][NN][20];
    __shared__ int                 s_idx[PPB][NN];
    __shared__ __align__(16) float s_dkp[PPB][KP][4];

    const int tid  = threadIdx.x;
    const int p    = tid >> 5;
    const int lane = tid & 31;
    const int n    = blockIdx.x * PPB + p;

    if (lane < KP)
        *(float4*)&s_dkp[p][lane][0] = ((const float4*)g_dkp)[n * KP + lane];
    __syncwarp();

    for (int a = lane; a < NN; a += 32) {
        float qx = query[n*3+0], qy = query[n*3+1], qz = query[n*3+2];
        int id = nbr[n*NN + a];
        s_idx[p][a] = id;
        float px = support[id*3+0] - qx;
        float py = support[id*3+1] - qy;
        float pz = support[id*3+2] - qz;
        float wl[16];
        #pragma unroll
        for (int k = 0; k < KP; k++) {
            float dx = px - s_dkp[p][k][0];
            float dy = py - s_dkp[p][k][1];
            float dz = pz - s_dkp[p][k][2];
            float sq = dx*dx + dy*dy + dz*dz;
            wl[k] = fmaxf(1.0f - 2.0f * sqrtf(sq), 0.0f);
        }
        wl[15] = 0.0f;
        #pragma unroll
        for (int j = 0; j < 4; j++)
            *(float4*)&s_w[p][a][j*4] = make_float4(wl[j*4+0], wl[j*4+1], wl[j*4+2], wl[j*4+3]);
    }
    __syncwarp();

    float2 acc[8][2];
    #pragma unroll
    for (int j = 0; j < 8; j++) { acc[j][0] = make_float2(0.f,0.f); acc[j][1] = make_float2(0.f,0.f); }

    GATHER_LOOP();

    // apply modulations (k=15 slot forced to 0)
    #pragma unroll
    for (int j = 0; j < 8; j++) {
        float mx = s_dkp[p][2*j][3];
        float my = (j < 7) ? s_dkp[p][2*j+1][3] : 0.f;
        acc[j][0].x *= mx; acc[j][0].y *= my;
        acc[j][1].x *= mx; acc[j][1].y *= my;
    }
    STORE_A(n);
}

// ---------------- warp-MMA GEMM mainloop ----------------
// D[128 x 64] = A[128 x 1024] * B[64 x 1024]^T, bf16 3-product split, 16 chunks of 64.
__device__ __forceinline__ void run_gemm_wm(const u32* __restrict__ B1g,
                                            const u32* __restrict__ B2g,
                                            char* smem, float* acc) {
    const int tid  = threadIdx.x;
    const int wid  = tid >> 5;
    const int lane = tid & 31;
    const int pt0  = blockIdx.x * MT;

    char* sA1 = smem + OFS_A1;
    char* sA2 = smem + OFS_A2;
    char* sB1 = smem + OFS_B1;
    char* sB2 = smem + OFS_B2;
    const uint32_t a1b = smem_u32(sA1), a2b = smem_u32(sA2);
    const uint32_t b1b = smem_u32(sB1), b2b = smem_u32(sB2);

    const uint32_t aoff = (uint32_t)(wid * 16 + (lane & 15)) * AS + ((lane >> 4) << 4);
    const uint32_t brow = (uint32_t)(((lane >> 4) << 3) + (lane & 7));
    const uint32_t boff = brow * AS + (((lane >> 3) & 1) << 4);

    #pragma unroll
    for (int i = 0; i < 32; i++) acc[i] = 0.f;

    #pragma unroll 1
    for (int c = 0; c < NCHUNK; c++) {
        for (int u = tid; u < 1024; u += 256) {
            int r = u >> 3, q = u & 7;
            const u32* s1 = g_A1 + (pt0 + r) * KW2 + c * 32 + q * 4;
            const u32* s2 = g_A2 + (pt0 + r) * KW2 + c * 32 + q * 4;
            *(uint4*)(sA1 + r * AS + q * 16) = *(const uint4*)s1;
            *(uint4*)(sA2 + r * AS + q * 16) = *(const uint4*)s2;
        }
        for (int u = tid; u < 512; u += 256) {
            int r = u >> 3, q = u & 7;
            *(uint4*)(sB1 + r * AS + q * 16) = *(const uint4*)(B1g + r * KW2 + c * 32 + q * 4);
            *(uint4*)(sB2 + r * AS + q * 16) = *(const uint4*)(B2g + r * KW2 + c * 32 + q * 4);
        }
        __syncthreads();

        #pragma unroll
        for (int ks = 0; ks < 4; ks++) {
            const uint32_t kb = (uint32_t)(ks * 32);
            uint32_t a1[4], a2[4];
            LDSM_X4(a1, a1b + aoff + kb);
            LDSM_X4(a2, a2b + aoff + kb);
            #pragma unroll
            for (int nb2 = 0; nb2 < 4; nb2++) {
                uint32_t b1[4], b2[4];
                uint32_t bo = (uint32_t)(nb2 * 16) * AS + boff + kb;
                LDSM_X4(b1, b1b + bo);
                LDSM_X4(b2, b2b + bo);
                float* d0 = acc + (nb2 * 2) * 4;
                float* d1 = acc + (nb2 * 2 + 1) * 4;
                MMA_BF16(d0, a1, b1[0], b1[1]);
                MMA_BF16(d1, a1, b1[2], b1[3]);
                MMA_BF16(d0, a1, b2[0], b2[1]);
                MMA_BF16(d1, a1, b2[2], b2[3]);
                MMA_BF16(d0, a2, b1[0], b1[1]);
                MMA_BF16(d1, a2, b1[2], b1[3]);
            }
        }
        __syncthreads();
    }
}

__device__ __forceinline__ void acc_to_smem(float* sx, const float* acc) {
    const int tid  = threadIdx.x;
    const int wid  = tid >> 5;
    const int lane = tid & 31;
    int r0 = wid * 16 + (lane >> 2);
    int cb = (lane & 3) * 2;
    #pragma unroll
    for (int nb = 0; nb < 8; nb++) {
        int col = nb * 8 + cb;
        sx[r0 * 68 + col]           = acc[nb * 4 + 0];
        sx[r0 * 68 + col + 1]       = acc[nb * 4 + 1];
        sx[(r0 + 8) * 68 + col]     = acc[nb * 4 + 2];
        sx[(r0 + 8) * 68 + col + 1] = acc[nb * 4 + 3];
    }
}

// ---------------- GEMM 1: f0 -> deformed kernel points + modulations ----------------
__global__ __launch_bounds__(256, 1) void gemm1_kernel(
    const float* __restrict__ obias, const float* __restrict__ kpts) {
    extern __shared__ __align__(16) char smem[];
    float acc[32];
    run_gemm_wm(g_OB1, g_OB2, smem, acc);

    float* sx = (float*)smem;
    acc_to_smem(sx, acc);
    __syncthreads();

    const int tid = threadIdx.x;
    if (tid < MT) {
        int n = blockIdx.x * MT + tid;
        float f0[60];
        #pragma unroll
        for (int i = 0; i < 60; i++) f0[i] = sx[tid * 68 + i] + obias[i];
        #pragma unroll
        for (int k = 0; k < KP; k++) {
            float4 o;
            o.x = kpts[k*3+0] + f0[3*k+0] * EXTENTF;
            o.y = kpts[k*3+1] + f0[3*k+1] * EXTENTF;
            o.z = kpts[k*3+2] + f0[3*k+2] * EXTENTF;
            o.w = 2.0f / (1.0f + expf(-f0[45 + k]));
            ((float4*)g_dkp)[n * KP + k] = o;
        }
    }
}

// ---------------- GEMM 2: x -> out + BN partials ----------------
__global__ __launch_bounds__(256, 1) void gemm2_kernel(float* __restrict__ out) {
    extern __shared__ __align__(16) char smem[];
    float acc[32];
    run_gemm_wm(g_WB1, g_WB2, smem, acc);

    float* sx = (float*)smem;
    acc_to_smem(sx, acc);
    __syncthreads();

    const int tid = threadIdx.x;
    {
        const int base4 = blockIdx.x * MT * OUTF / 4;
        for (int v = tid; v < MT * OUTF / 4; v += 256) {
            int pl = v >> 4, j = v & 15;
            float4 val = *(float4*)&sx[pl * 68 + j * 4];
            ((float4*)out)[base4 + v] = val;
        }
    }
    if (tid < OUTF) {
        float s = 0.f, s2 = 0.f;
        for (int pl = 0; pl < MT; pl++) {
            float v = sx[pl * 68 + tid];
            s += v; s2 += v * v;
        }
        g_psum  [blockIdx.x * OUTF + tid] = s;
        g_psumsq[blockIdx.x * OUTF + tid] = s2;
    }
}

// ---------------- BN stats ----------------
__global__ void stats_kernel(const float* __restrict__ gamma, const float* __restrict__ beta) {
    int o = blockIdx.x;
    int tid = threadIdx.x;
    float s = 0.f, s2 = 0.f;
    for (int j = tid; j < NGEMM; j += blockDim.x) {
        s  += g_psum  [j * OUTF + o];
        s2 += g_psumsq[j * OUTF + o];
    }
    __shared__ float sh[256], sh2[256];
    sh[tid] = s; sh2[tid] = s2;
    __syncthreads();
    for (int st = 128; st > 0; st >>= 1) {
        if (tid < st) { sh[tid] += sh[tid + st]; sh2[tid] += sh2[tid + st]; }
        __syncthreads();
    }
    if (tid == 0) {
        float mean = sh[0]  / (float)NPTS;
        float var  = sh2[0] / (float)NPTS - mean * mean;
        float sc   = rsqrtf(var + 1e-6f) * gamma[o];
        g_scale[o] = sc;
        g_shift[o] = beta[o] - mean * sc;
    }
}

// ---------------- BN apply + LeakyReLU ----------------
__global__ void bn_kernel(float* __restrict__ out) {
    const int total4 = NPTS * OUTF / 4;
    for (int i = blockIdx.x * blockDim.x + threadIdx.x; i < total4; i += gridDim.x * blockDim.x) {
        float4 v = ((float4*)out)[i];
        int ch = (i & 15) * 4;
        float4 sc = *(const float4*)&g_scale[ch];
        float4 sh = *(const float4*)&g_shift[ch];
        v.x = v.x * sc.x + sh.x;  v.x = v.x >= 0.f ? v.x : 0.1f * v.x;
        v.y = v.y * sc.y + sh.y;  v.y = v.y >= 0.f ? v.y : 0.1f * v.y;
        v.z = v.z * sc.z + sh.z;  v.z = v.z >= 0.f ? v.z : 0.1f * v.z;
        v.w = v.w * sc.w + sh.w;  v.w = v.w >= 0.f ? v.w : 0.1f * v.w;
        ((float4*)out)[i] = v;
    }
}

// ---------------- launch ----------------
extern "C" void kernel_launch(void* const* d_in, const int* in_sizes, int n_in,
                              void* d_out, int out_size) {
    const float* query   = (const float*)d_in[0];
    const float* support = (const float*)d_in[1];
    const int*   nbr     = (const int*)  d_in[2];
    const float* feat    = (const float*)d_in[3];
    const float* weight  = (const float*)d_in[4];
    const float* ow      = (const float*)d_in[5];
    const float* obias   = (const float*)d_in[6];
    const float* gamma   = (const float*)d_in[7];
    const float* beta    = (const float*)d_in[8];
    const float* kpts    = (const float*)d_in[9];
    float* out = (float*)d_out;

    static int attr_set = 0;
    if (!attr_set) {
        cudaFuncSetAttribute(gemm1_kernel, cudaFuncAttributeMaxDynamicSharedMemorySize, SM_GEMM);
        cudaFuncSetAttribute(gemm2_kernel, cudaFuncAttributeMaxDynamicSharedMemorySize, SM_GEMM);
        attr_set = 1;
    }

    prep_kernel   <<<64, 256>>>(ow, weight);
    gather1_kernel<<<NBLK_G, TPB>>>(query, support, nbr, feat, kpts);
    gemm1_kernel  <<<NGEMM, 256, SM_GEMM>>>(obias, kpts);
    gather2_kernel<<<NBLK_G, TPB>>>(query, support, nbr, feat);
    gemm2_kernel  <<<NGEMM, 256, SM_GEMM>>>(out);
    stats_kernel  <<<OUTF, 256>>>(gamma, beta);
    bn_kernel     <<<2048, 256>>>(out);
}

// round 13
// speedup vs baseline: 1.7957x; 1.0923x over previous
#include <cuda_runtime.h>
#include <cuda_bf16.h>
#include <math.h>
#include <stdint.h>

#define NPTS   65536
#define NN     34
#define KP     15
#define INF    64
#define OUTF   64
#define EXTENTF 0.5f
#define PPB    4                  // points per gather CTA (1 warp each)
#define TPB_G  128
#define NBLK_G (NPTS / PPB)       // 16384 gather CTAs
#define KW2    512                // u32 words per A/B row (bf16 pairs), K'=1024 (i' = c*16+k, k=15 pad)
#define MT     128                // GEMM tile M
#define NGEMM  (NPTS / MT)        // 512 GEMM CTAs
#define NCHUNK 16                 // 1024 / 64

// GEMM smem: padded tiles, row stride 144B (72 bf16) -> conflict-free ldmatrix
#define AS      144
#define OFS_A1  0
#define OFS_A2  18432
#define OFS_B1  36864
#define OFS_B2  46080
#define SM_GEMM 55296

typedef unsigned long long u64;
typedef unsigned int u32;

// ---------------- device scratch ----------------
__device__ __align__(16) u32 g_A1[NPTS * KW2];    // wf hi  (bf16 pairs, i' = c*16+k)
__device__ __align__(16) u32 g_A2[NPTS * KW2];    // wf residual
__device__ __align__(16) u32 g_OB1[64 * KW2];     // offset_weight^T hi [d][i'] pairs
__device__ __align__(16) u32 g_OB2[64 * KW2];
__device__ __align__(16) u32 g_WB1[64 * KW2];     // weight^T hi [o][i'] pairs
__device__ __align__(16) u32 g_WB2[64 * KW2];
__device__ __align__(16) float g_dkp[NPTS * KP * 4];  // deformed kp xyz + modulation
__device__ float g_psum  [NGEMM * OUTF];
__device__ float g_psumsq[NGEMM * OUTF];
__device__ __align__(16) float g_scale[OUTF];
__device__ __align__(16) float g_shift[OUTF];

// ---------------- helpers ----------------
__device__ __forceinline__ void f2fma(float2 &acc, float2 a, float2 b) {
    asm("{\n\t"
        ".reg .b64 ra, rb, rc;\n\t"
        "mov.b64 ra, {%2, %3};\n\t"
        "mov.b64 rb, {%4, %5};\n\t"
        "mov.b64 rc, {%0, %1};\n\t"
        "fma.rn.f32x2 rc, ra, rb, rc;\n\t"
        "mov.b64 {%0, %1}, rc;\n\t"
        "}"
        : "+f"(acc.x), "+f"(acc.y)
        : "f"(a.x), "f"(a.y), "f"(b.x), "f"(b.y));
}

__device__ __forceinline__ uint32_t smem_u32(const void* p) {
    uint32_t a;
    asm("{ .reg .u64 t; cvta.to.shared.u64 t, %1; cvt.u32.u64 %0, t; }" : "=r"(a) : "l"(p));
    return a;
}

#define LDSM_X4(r, addr)                                                          \
    asm volatile("ldmatrix.sync.aligned.m8n8.x4.shared.b16 {%0,%1,%2,%3}, [%4];"  \
        : "=r"((r)[0]), "=r"((r)[1]), "=r"((r)[2]), "=r"((r)[3]) : "r"(addr))

#define MMA_BF16(d, a, b0, b1)                                                    \
    asm volatile("mma.sync.aligned.m16n8k16.row.col.f32.bf16.bf16.f32 "           \
        "{%0,%1,%2,%3}, {%4,%5,%6,%7}, {%8,%9}, {%0,%1,%2,%3};"                   \
        : "+f"((d)[0]), "+f"((d)[1]), "+f"((d)[2]), "+f"((d)[3])                  \
        : "r"((a)[0]), "r"((a)[1]), "r"((a)[2]), "r"((a)[3]), "r"(b0), "r"(b1))

__device__ __forceinline__ u32 pack_bf16(float lo, float hi) {
    __nv_bfloat162 h = __floats2bfloat162_rn(lo, hi);
    return *(u32*)&h;
}
__device__ __forceinline__ float bf16_res(float v) {
    return v - __bfloat162float(__float2bfloat16_rn(v));
}

// ---------------- prep: hi/lo bf16 transposed weight matrices, i' = c*16+k order ----------------
__global__ void prep_kernel(const float* __restrict__ ow, const float* __restrict__ w) {
    int t = blockIdx.x * blockDim.x + threadIdx.x;
    int stride = gridDim.x * blockDim.x;
    for (int idx = t; idx < 64 * KW2; idx += stride) {
        int row = idx / KW2, j = idx - row * KW2;
        int ip0 = 2 * j, ip1 = 2 * j + 1;
        int c0 = ip0 >> 4, k0 = ip0 & 15;
        int c1 = ip1 >> 4, k1 = ip1 & 15;
        // offset_weight [i=k*64+c][d=60]
        float v0 = (k0 < 15 && row < 60) ? ow[(k0 * 64 + c0) * 60 + row] : 0.f;
        float v1 = (k1 < 15 && row < 60) ? ow[(k1 * 64 + c1) * 60 + row] : 0.f;
        g_OB1[idx] = pack_bf16(v0, v1);
        g_OB2[idx] = pack_bf16(bf16_res(v0), bf16_res(v1));
        // weight [i=k*64+c][o=64]
        float u0 = (k0 < 15) ? w[(k0 * 64 + c0) * 64 + row] : 0.f;
        float u1 = (k1 < 15) ? w[(k1 * 64 + c1) * 64 + row] : 0.f;
        g_WB1[idx] = pack_bf16(u0, u1);
        g_WB2[idx] = pack_bf16(bf16_res(u0), bf16_res(u1));
    }
}

// ---------------- gather inner loop: warp per point, 2 channels per lane ----------------
// acc[j][h]: j = k-pair (k=2j, 2j+1), h = channel half (c = lane + 32h)
#define GATHER_LOOP() do {                                                       \
    _Pragma("unroll 2")                                                          \
    for (int a = 0; a < NN; a++) {                                               \
        int id = s_idx[p][a];                                                    \
        float f0 = feat[id * INF + lane];                                        \
        float f1 = feat[id * INF + 32 + lane];                                   \
        float2 ff0 = make_float2(f0, f0);                                        \
        float2 ff1 = make_float2(f1, f1);                                        \
        const float4* wr = (const float4*)&s_w[p][a][0];                         \
        float4 w0 = wr[0], w1 = wr[1], w2 = wr[2], w3 = wr[3];                   \
        f2fma(acc[0][0], make_float2(w0.x, w0.y), ff0);                          \
        f2fma(acc[0][1], make_float2(w0.x, w0.y), ff1);                          \
        f2fma(acc[1][0], make_float2(w0.z, w0.w), ff0);                          \
        f2fma(acc[1][1], make_float2(w0.z, w0.w), ff1);                          \
        f2fma(acc[2][0], make_float2(w1.x, w1.y), ff0);                          \
        f2fma(acc[2][1], make_float2(w1.x, w1.y), ff1);                          \
        f2fma(acc[3][0], make_float2(w1.z, w1.w), ff0);                          \
        f2fma(acc[3][1], make_float2(w1.z, w1.w), ff1);                          \
        f2fma(acc[4][0], make_float2(w2.x, w2.y), ff0);                          \
        f2fma(acc[4][1], make_float2(w2.x, w2.y), ff1);                          \
        f2fma(acc[5][0], make_float2(w2.z, w2.w), ff0);                          \
        f2fma(acc[5][1], make_float2(w2.z, w2.w), ff1);                          \
        f2fma(acc[6][0], make_float2(w3.x, w3.y), ff0);                          \
        f2fma(acc[6][1], make_float2(w3.x, w3.y), ff1);                          \
        f2fma(acc[7][0], make_float2(w3.z, w3.w), ff0);                          \
        f2fma(acc[7][1], make_float2(w3.z, w3.w), ff1);                          \
    }                                                                            \
} while (0)

// direct bf16 hi/res pack + store: lane writes 8 pairs per channel half
#define STORE_A(nn) do {                                                         \
    _Pragma("unroll")                                                            \
    for (int h = 0; h < 2; h++) {                                                \
        int c = lane + h * 32;                                                   \
        u32 base = (u32)(nn) * KW2 + (u32)c * 8;                                 \
        uint4 hi0, hi1, lo0, lo1;                                                \
        hi0.x = pack_bf16(acc[0][h].x, acc[0][h].y);                             \
        hi0.y = pack_bf16(acc[1][h].x, acc[1][h].y);                             \
        hi0.z = pack_bf16(acc[2][h].x, acc[2][h].y);                             \
        hi0.w = pack_bf16(acc[3][h].x, acc[3][h].y);                             \
        hi1.x = pack_bf16(acc[4][h].x, acc[4][h].y);                             \
        hi1.y = pack_bf16(acc[5][h].x, acc[5][h].y);                             \
        hi1.z = pack_bf16(acc[6][h].x, acc[6][h].y);                             \
        hi1.w = pack_bf16(acc[7][h].x, acc[7][h].y);                             \
        lo0.x = pack_bf16(bf16_res(acc[0][h].x), bf16_res(acc[0][h].y));         \
        lo0.y = pack_bf16(bf16_res(acc[1][h].x), bf16_res(acc[1][h].y));         \
        lo0.z = pack_bf16(bf16_res(acc[2][h].x), bf16_res(acc[2][h].y));         \
        lo0.w = pack_bf16(bf16_res(acc[3][h].x), bf16_res(acc[3][h].y));         \
        lo1.x = pack_bf16(bf16_res(acc[4][h].x), bf16_res(acc[4][h].y));         \
        lo1.y = pack_bf16(bf16_res(acc[5][h].x), bf16_res(acc[5][h].y));         \
        lo1.z = pack_bf16(bf16_res(acc[6][h].x), bf16_res(acc[6][h].y));         \
        lo1.w = pack_bf16(bf16_res(acc[7][h].x), bf16_res(acc[7][h].y));         \
        *(uint4*)&g_A1[base]     = hi0;                                          \
        *(uint4*)&g_A1[base + 4] = hi1;                                          \
        *(uint4*)&g_A2[base]     = lo0;                                          \
        *(uint4*)&g_A2[base + 4] = lo1;                                          \
    }                                                                            \
} while (0)

// ---------------- gather 1: rigid weights -> wf0 -> A (bf16 split) ----------------
__global__ __launch_bounds__(TPB_G, 6) void gather1_kernel(
    const float* __restrict__ query, const float* __restrict__ support,
    const int* __restrict__ nbr, const float* __restrict__ feat,
    const float* __restrict__ kpts)
{
    __shared__ __align__(16) float s_w [PPB][NN][20];
    __shared__ int                 s_idx[PPB][NN];

    const int tid  = threadIdx.x;
    const int p    = tid >> 5;
    const int lane = tid & 31;
    const int n    = blockIdx.x * PPB + p;

    {
        float qx = query[n*3+0], qy = query[n*3+1], qz = query[n*3+2];
        for (int a = lane; a < NN; a += 32) {
            int id = nbr[n*NN + a];
            s_idx[p][a] = id;
            float px = support[id*3+0] - qx;
            float py = support[id*3+1] - qy;
            float pz = support[id*3+2] - qz;
            float wl[16];
            #pragma unroll
            for (int k = 0; k < KP; k++) {
                float dx = px - kpts[k*3+0];
                float dy = py - kpts[k*3+1];
                float dz = pz - kpts[k*3+2];
                float sq = dx*dx + dy*dy + dz*dz;
                wl[k] = fmaxf(1.0f - 2.0f * sqrtf(sq), 0.0f);
            }
            wl[15] = 0.0f;
            #pragma unroll
            for (int j = 0; j < 4; j++)
                *(float4*)&s_w[p][a][j*4] = make_float4(wl[j*4+0], wl[j*4+1], wl[j*4+2], wl[j*4+3]);
        }
    }
    __syncwarp();

    float2 acc[8][2];
    #pragma unroll
    for (int j = 0; j < 8; j++) { acc[j][0] = make_float2(0.f,0.f); acc[j][1] = make_float2(0.f,0.f); }

    GATHER_LOOP();
    STORE_A(n);
}

// ---------------- gather 2: deformed weights (+mod) -> wf -> A (bf16 split) ----------------
__global__ __launch_bounds__(TPB_G, 6) void gather2_kernel(
    const float* __restrict__ query, const float* __restrict__ support,
    const int* __restrict__ nbr, const float* __restrict__ feat)
{
    __shared__ __align__(16) float s_w  [PPB][NN][20];
    __shared__ int                 s_idx[PPB][NN];
    __shared__ __align__(16) float s_dkp[PPB][KP][4];

    const int tid  = threadIdx.x;
    const int p    = tid >> 5;
    const int lane = tid & 31;
    const int n    = blockIdx.x * PPB + p;

    if (lane < KP)
        *(float4*)&s_dkp[p][lane][0] = ((const float4*)g_dkp)[n * KP + lane];
    __syncwarp();

    {
        float qx = query[n*3+0], qy = query[n*3+1], qz = query[n*3+2];
        for (int a = lane; a < NN; a += 32) {
            int id = nbr[n*NN + a];
            s_idx[p][a] = id;
            float px = support[id*3+0] - qx;
            float py = support[id*3+1] - qy;
            float pz = support[id*3+2] - qz;
            float wl[16];
            #pragma unroll
            for (int k = 0; k < KP; k++) {
                float dx = px - s_dkp[p][k][0];
                float dy = py - s_dkp[p][k][1];
                float dz = pz - s_dkp[p][k][2];
                float sq = dx*dx + dy*dy + dz*dz;
                wl[k] = fmaxf(1.0f - 2.0f * sqrtf(sq), 0.0f);
            }
            wl[15] = 0.0f;
            #pragma unroll
            for (int j = 0; j < 4; j++)
                *(float4*)&s_w[p][a][j*4] = make_float4(wl[j*4+0], wl[j*4+1], wl[j*4+2], wl[j*4+3]);
        }
    }
    __syncwarp();

    float2 acc[8][2];
    #pragma unroll
    for (int j = 0; j < 8; j++) { acc[j][0] = make_float2(0.f,0.f); acc[j][1] = make_float2(0.f,0.f); }

    GATHER_LOOP();

    // apply modulations (k=15 slot forced to 0)
    #pragma unroll
    for (int j = 0; j < 8; j++) {
        float mx = s_dkp[p][2*j][3];
        float my = (j < 7) ? s_dkp[p][2*j+1][3] : 0.f;
        acc[j][0].x *= mx; acc[j][0].y *= my;
        acc[j][1].x *= mx; acc[j][1].y *= my;
    }
    STORE_A(n);
}

// ---------------- warp-MMA GEMM mainloop ----------------
// D[128 x 64] = A[128 x 1024] * B[64 x 1024]^T, bf16 3-product split, 16 chunks of 64.
__device__ __forceinline__ void run_gemm_wm(const u32* __restrict__ B1g,
                                            const u32* __restrict__ B2g,
                                            char* smem, float* acc) {
    const int tid  = threadIdx.x;
    const int wid  = tid >> 5;
    const int lane = tid & 31;
    const int pt0  = blockIdx.x * MT;

    char* sA1 = smem + OFS_A1;
    char* sA2 = smem + OFS_A2;
    char* sB1 = smem + OFS_B1;
    char* sB2 = smem + OFS_B2;
    const uint32_t a1b = smem_u32(sA1), a2b = smem_u32(sA2);
    const uint32_t b1b = smem_u32(sB1), b2b = smem_u32(sB2);

    const uint32_t aoff = (uint32_t)(wid * 16 + (lane & 15)) * AS + ((lane >> 4) << 4);
    const uint32_t brow = (uint32_t)(((lane >> 4) << 3) + (lane & 7));
    const uint32_t boff = brow * AS + (((lane >> 3) & 1) << 4);

    #pragma unroll
    for (int i = 0; i < 32; i++) acc[i] = 0.f;

    #pragma unroll 1
    for (int c = 0; c < NCHUNK; c++) {
        for (int u = tid; u < 1024; u += 256) {
            int r = u >> 3, q = u & 7;
            const u32* s1 = g_A1 + (pt0 + r) * KW2 + c * 32 + q * 4;
            const u32* s2 = g_A2 + (pt0 + r) * KW2 + c * 32 + q * 4;
            *(uint4*)(sA1 + r * AS + q * 16) = *(const uint4*)s1;
            *(uint4*)(sA2 + r * AS + q * 16) = *(const uint4*)s2;
        }
        for (int u = tid; u < 512; u += 256) {
            int r = u >> 3, q = u & 7;
            *(uint4*)(sB1 + r * AS + q * 16) = *(const uint4*)(B1g + r * KW2 + c * 32 + q * 4);
            *(uint4*)(sB2 + r * AS + q * 16) = *(const uint4*)(B2g + r * KW2 + c * 32 + q * 4);
        }
        __syncthreads();

        #pragma unroll
        for (int ks = 0; ks < 4; ks++) {
            const uint32_t kb = (uint32_t)(ks * 32);
            uint32_t a1[4], a2[4];
            LDSM_X4(a1, a1b + aoff + kb);
            LDSM_X4(a2, a2b + aoff + kb);
            #pragma unroll
            for (int nb2 = 0; nb2 < 4; nb2++) {
                uint32_t b1[4], b2[4];
                uint32_t bo = (uint32_t)(nb2 * 16) * AS + boff + kb;
                LDSM_X4(b1, b1b + bo);
                LDSM_X4(b2, b2b + bo);
                float* d0 = acc + (nb2 * 2) * 4;
                float* d1 = acc + (nb2 * 2 + 1) * 4;
                MMA_BF16(d0, a1, b1[0], b1[1]);
                MMA_BF16(d1, a1, b1[2], b1[3]);
                MMA_BF16(d0, a1, b2[0], b2[1]);
                MMA_BF16(d1, a1, b2[2], b2[3]);
                MMA_BF16(d0, a2, b1[0], b1[1]);
                MMA_BF16(d1, a2, b1[2], b1[3]);
            }
        }
        __syncthreads();
    }
}

__device__ __forceinline__ void acc_to_smem(float* sx, const float* acc) {
    const int tid  = threadIdx.x;
    const int wid  = tid >> 5;
    const int lane = tid & 31;
    int r0 = wid * 16 + (lane >> 2);
    int cb = (lane & 3) * 2;
    #pragma unroll
    for (int nb = 0; nb < 8; nb++) {
        int col = nb * 8 + cb;
        sx[r0 * 68 + col]           = acc[nb * 4 + 0];
        sx[r0 * 68 + col + 1]       = acc[nb * 4 + 1];
        sx[(r0 + 8) * 68 + col]     = acc[nb * 4 + 2];
        sx[(r0 + 8) * 68 + col + 1] = acc[nb * 4 + 3];
    }
}

// ---------------- GEMM 1: f0 -> deformed kernel points + modulations ----------------
__global__ __launch_bounds__(256, 1) void gemm1_kernel(
    const float* __restrict__ obias, const float* __restrict__ kpts) {
    extern __shared__ __align__(16) char smem[];
    float acc[32];
    run_gemm_wm(g_OB1, g_OB2, smem, acc);

    float* sx = (float*)smem;
    acc_to_smem(sx, acc);
    __syncthreads();

    const int tid = threadIdx.x;
    if (tid < MT) {
        int n = blockIdx.x * MT + tid;
        float f0[60];
        #pragma unroll
        for (int i = 0; i < 60; i++) f0[i] = sx[tid * 68 + i] + obias[i];
        #pragma unroll
        for (int k = 0; k < KP; k++) {
            float4 o;
            o.x = kpts[k*3+0] + f0[3*k+0] * EXTENTF;
            o.y = kpts[k*3+1] + f0[3*k+1] * EXTENTF;
            o.z = kpts[k*3+2] + f0[3*k+2] * EXTENTF;
            o.w = 2.0f / (1.0f + expf(-f0[45 + k]));
            ((float4*)g_dkp)[n * KP + k] = o;
        }
    }
}

// ---------------- GEMM 2: x -> out + BN partials ----------------
__global__ __launch_bounds__(256, 1) void gemm2_kernel(float* __restrict__ out) {
    extern __shared__ __align__(16) char smem[];
    float acc[32];
    run_gemm_wm(g_WB1, g_WB2, smem, acc);

    float* sx = (float*)smem;
    acc_to_smem(sx, acc);
    __syncthreads();

    const int tid = threadIdx.x;
    {
        const int base4 = blockIdx.x * MT * OUTF / 4;
        for (int v = tid; v < MT * OUTF / 4; v += 256) {
            int pl = v >> 4, j = v & 15;
            float4 val = *(float4*)&sx[pl * 68 + j * 4];
            ((float4*)out)[base4 + v] = val;
        }
    }
    if (tid < OUTF) {
        float s = 0.f, s2 = 0.f;
        for (int pl = 0; pl < MT; pl++) {
            float v = sx[pl * 68 + tid];
            s += v; s2 += v * v;
        }
        g_psum  [blockIdx.x * OUTF + tid] = s;
        g_psumsq[blockIdx.x * OUTF + tid] = s2;
    }
}

// ---------------- BN stats ----------------
__global__ void stats_kernel(const float* __restrict__ gamma, const float* __restrict__ beta) {
    int o = blockIdx.x;
    int tid = threadIdx.x;
    float s = 0.f, s2 = 0.f;
    for (int j = tid; j < NGEMM; j += blockDim.x) {
        s  += g_psum  [j * OUTF + o];
        s2 += g_psumsq[j * OUTF + o];
    }
    __shared__ float sh[256], sh2[256];
    sh[tid] = s; sh2[tid] = s2;
    __syncthreads();
    for (int st = 128; st > 0; st >>= 1) {
        if (tid < st) { sh[tid] += sh[tid + st]; sh2[tid] += sh2[tid + st]; }
        __syncthreads();
    }
    if (tid == 0) {
        float mean = sh[0]  / (float)NPTS;
        float var  = sh2[0] / (float)NPTS - mean * mean;
        float sc   = rsqrtf(var + 1e-6f) * gamma[o];
        g_scale[o] = sc;
        g_shift[o] = beta[o] - mean * sc;
    }
}

// ---------------- BN apply + LeakyReLU ----------------
__global__ void bn_kernel(float* __restrict__ out) {
    const int total4 = NPTS * OUTF / 4;
    for (int i = blockIdx.x * blockDim.x + threadIdx.x; i < total4; i += gridDim.x * blockDim.x) {
        float4 v = ((float4*)out)[i];
        int ch = (i & 15) * 4;
        float4 sc = *(const float4*)&g_scale[ch];
        float4 sh = *(const float4*)&g_shift[ch];
        v.x = v.x * sc.x + sh.x;  v.x = v.x >= 0.f ? v.x : 0.1f * v.x;
        v.y = v.y * sc.y + sh.y;  v.y = v.y >= 0.f ? v.y : 0.1f * v.y;
        v.z = v.z * sc.z + sh.z;  v.z = v.z >= 0.f ? v.z : 0.1f * v.z;
        v.w = v.w * sc.w + sh.w;  v.w = v.w >= 0.f ? v.w : 0.1f * v.w;
        ((float4*)out)[i] = v;
    }
}

// ---------------- launch ----------------
extern "C" void kernel_launch(void* const* d_in, const int* in_sizes, int n_in,
                              void* d_out, int out_size) {
    const float* query   = (const float*)d_in[0];
    const float* support = (const float*)d_in[1];
    const int*   nbr     = (const int*)  d_in[2];
    const float* feat    = (const float*)d_in[3];
    const float* weight  = (const float*)d_in[4];
    const float* ow      = (const float*)d_in[5];
    const float* obias   = (const float*)d_in[6];
    const float* gamma   = (const float*)d_in[7];
    const float* beta    = (const float*)d_in[8];
    const float* kpts    = (const float*)d_in[9];
    float* out = (float*)d_out;

    static int attr_set = 0;
    if (!attr_set) {
        cudaFuncSetAttribute(gemm1_kernel, cudaFuncAttributeMaxDynamicSharedMemorySize, SM_GEMM);
        cudaFuncSetAttribute(gemm2_kernel, cudaFuncAttributeMaxDynamicSharedMemorySize, SM_GEMM);
        attr_set = 1;
    }

    prep_kernel   <<<64, 256>>>(ow, weight);
    gather1_kernel<<<NBLK_G, TPB_G>>>(query, support, nbr, feat, kpts);
    gemm1_kernel  <<<NGEMM, 256, SM_GEMM>>>(obias, kpts);
    gather2_kernel<<<NBLK_G, TPB_G>>>(query, support, nbr, feat);
    gemm2_kernel  <<<NGEMM, 256, SM_GEMM>>>(out);
    stats_kernel  <<<OUTF, 256>>>(gamma, beta);
    bn_kernel     <<<2048, 256>>>(out);
}

// round 14
// speedup vs baseline: 2.2746x; 1.2667x over previous
#include <cuda_runtime.h>
#include <cuda_bf16.h>
#include <math.h>
#include <stdint.h>

#define NPTS   65536
#define NN     34
#define KP     15
#define INF    64
#define OUTF   64
#define EXTENTF 0.5f
#define PPB    4                  // points per gather CTA (1 warp each)
#define TPB_G  128
#define NBLK_G (NPTS / PPB)       // 16384 gather CTAs
#define KW2    512                // u32 words per A/B row (bf16 pairs), K'=1024 (i' = c*16+k, k=15 pad)
#define MT     128                // GEMM tile M
#define NGEMM  (NPTS / MT)        // 512 GEMM CTAs
#define NCHUNK 16                 // 1024 / 64

// GEMM smem: padded tiles, row stride 144B (72 bf16) -> conflict-free ldmatrix
// Double-buffered: two 55296B buffers.
#define AS      144
#define OFS_A1  0
#define OFS_A2  18432
#define OFS_B1  36864
#define OFS_B2  46080
#define BUFSZ   55296
#define SM_GEMM (2 * BUFSZ)       // 110592 B

typedef unsigned long long u64;
typedef unsigned int u32;

// ---------------- device scratch ----------------
__device__ __align__(16) u32 g_A1[NPTS * KW2];    // wf hi  (bf16 pairs, i' = c*16+k)
__device__ __align__(16) u32 g_A2[NPTS * KW2];    // wf residual
__device__ __align__(16) u32 g_OB1[64 * KW2];     // offset_weight^T hi [d][i'] pairs
__device__ __align__(16) u32 g_OB2[64 * KW2];
__device__ __align__(16) u32 g_WB1[64 * KW2];     // weight^T hi [o][i'] pairs
__device__ __align__(16) u32 g_WB2[64 * KW2];
__device__ __align__(16) float g_dkp[NPTS * KP * 4];  // deformed kp xyz + modulation
__device__ float g_psum  [NGEMM * OUTF];
__device__ float g_psumsq[NGEMM * OUTF];
__device__ __align__(16) float g_scale[OUTF];
__device__ __align__(16) float g_shift[OUTF];

// ---------------- helpers ----------------
__device__ __forceinline__ void f2fma(float2 &acc, float2 a, float2 b) {
    asm("{\n\t"
        ".reg .b64 ra, rb, rc;\n\t"
        "mov.b64 ra, {%2, %3};\n\t"
        "mov.b64 rb, {%4, %5};\n\t"
        "mov.b64 rc, {%0, %1};\n\t"
        "fma.rn.f32x2 rc, ra, rb, rc;\n\t"
        "mov.b64 {%0, %1}, rc;\n\t"
        "}"
        : "+f"(acc.x), "+f"(acc.y)
        : "f"(a.x), "f"(a.y), "f"(b.x), "f"(b.y));
}

__device__ __forceinline__ uint32_t smem_u32(const void* p) {
    uint32_t a;
    asm("{ .reg .u64 t; cvta.to.shared.u64 t, %1; cvt.u32.u64 %0, t; }" : "=r"(a) : "l"(p));
    return a;
}

#define CP_ASYNC16(dst, src)                                                      \
    asm volatile("{ .reg .u64 g; cvta.to.global.u64 g, %1; "                      \
                 "cp.async.cg.shared.global [%0], [g], 16; }"                     \
                 :: "r"(dst), "l"(src) : "memory")
#define CP_COMMIT() asm volatile("cp.async.commit_group;" ::: "memory")
#define CP_WAIT0()  asm volatile("cp.async.wait_group 0;" ::: "memory")

#define LDSM_X4(r, addr)                                                          \
    asm volatile("ldmatrix.sync.aligned.m8n8.x4.shared.b16 {%0,%1,%2,%3}, [%4];"  \
        : "=r"((r)[0]), "=r"((r)[1]), "=r"((r)[2]), "=r"((r)[3]) : "r"(addr))

#define MMA_BF16(d, a, b0, b1)                                                    \
    asm volatile("mma.sync.aligned.m16n8k16.row.col.f32.bf16.bf16.f32 "           \
        "{%0,%1,%2,%3}, {%4,%5,%6,%7}, {%8,%9}, {%0,%1,%2,%3};"                   \
        : "+f"((d)[0]), "+f"((d)[1]), "+f"((d)[2]), "+f"((d)[3])                  \
        : "r"((a)[0]), "r"((a)[1]), "r"((a)[2]), "r"((a)[3]), "r"(b0), "r"(b1))

__device__ __forceinline__ u32 pack_bf16(float lo, float hi) {
    __nv_bfloat162 h = __floats2bfloat162_rn(lo, hi);
    return *(u32*)&h;
}
__device__ __forceinline__ float bf16_res(float v) {
    return v - __bfloat162float(__float2bfloat16_rn(v));
}

// ---------------- prep: hi/lo bf16 transposed weight matrices, i' = c*16+k order ----------------
__global__ void prep_kernel(const float* __restrict__ ow, const float* __restrict__ w) {
    int t = blockIdx.x * blockDim.x + threadIdx.x;
    int stride = gridDim.x * blockDim.x;
    for (int idx = t; idx < 64 * KW2; idx += stride) {
        int row = idx / KW2, j = idx - row * KW2;
        int ip0 = 2 * j, ip1 = 2 * j + 1;
        int c0 = ip0 >> 4, k0 = ip0 & 15;
        int c1 = ip1 >> 4, k1 = ip1 & 15;
        // offset_weight [i=k*64+c][d=60]
        float v0 = (k0 < 15 && row < 60) ? ow[(k0 * 64 + c0) * 60 + row] : 0.f;
        float v1 = (k1 < 15 && row < 60) ? ow[(k1 * 64 + c1) * 60 + row] : 0.f;
        g_OB1[idx] = pack_bf16(v0, v1);
        g_OB2[idx] = pack_bf16(bf16_res(v0), bf16_res(v1));
        // weight [i=k*64+c][o=64]
        float u0 = (k0 < 15) ? w[(k0 * 64 + c0) * 64 + row] : 0.f;
        float u1 = (k1 < 15) ? w[(k1 * 64 + c1) * 64 + row] : 0.f;
        g_WB1[idx] = pack_bf16(u0, u1);
        g_WB2[idx] = pack_bf16(bf16_res(u0), bf16_res(u1));
    }
}

// ---------------- gather inner loop: warp per point, 2 channels per lane ----------------
// acc[j][h]: j = k-pair (k=2j, 2j+1), h = channel half (c = lane + 32h)
#define GATHER_LOOP() do {                                                       \
    _Pragma("unroll 2")                                                          \
    for (int a = 0; a < NN; a++) {                                               \
        int id = s_idx[p][a];                                                    \
        float f0 = feat[id * INF + lane];                                        \
        float f1 = feat[id * INF + 32 + lane];                                   \
        float2 ff0 = make_float2(f0, f0);                                        \
        float2 ff1 = make_float2(f1, f1);                                        \
        const float4* wr = (const float4*)&s_w[p][a][0];                         \
        float4 w0 = wr[0], w1 = wr[1], w2 = wr[2], w3 = wr[3];                   \
        f2fma(acc[0][0], make_float2(w0.x, w0.y), ff0);                          \
        f2fma(acc[0][1], make_float2(w0.x, w0.y), ff1);                          \
        f2fma(acc[1][0], make_float2(w0.z, w0.w), ff0);                          \
        f2fma(acc[1][1], make_float2(w0.z, w0.w), ff1);                          \
        f2fma(acc[2][0], make_float2(w1.x, w1.y), ff0);                          \
        f2fma(acc[2][1], make_float2(w1.x, w1.y), ff1);                          \
        f2fma(acc[3][0], make_float2(w1.z, w1.w), ff0);                          \
        f2fma(acc[3][1], make_float2(w1.z, w1.w), ff1);                          \
        f2fma(acc[4][0], make_float2(w2.x, w2.y), ff0);                          \
        f2fma(acc[4][1], make_float2(w2.x, w2.y), ff1);                          \
        f2fma(acc[5][0], make_float2(w2.z, w2.w), ff0);                          \
        f2fma(acc[5][1], make_float2(w2.z, w2.w), ff1);                          \
        f2fma(acc[6][0], make_float2(w3.x, w3.y), ff0);                          \
        f2fma(acc[6][1], make_float2(w3.x, w3.y), ff1);                          \
        f2fma(acc[7][0], make_float2(w3.z, w3.w), ff0);                          \
        f2fma(acc[7][1], make_float2(w3.z, w3.w), ff1);                          \
    }                                                                            \
} while (0)

// direct bf16 hi/res pack + store: lane writes 8 pairs per channel half
#define STORE_A(nn) do {                                                         \
    _Pragma("unroll")                                                            \
    for (int h = 0; h < 2; h++) {                                                \
        int c = lane + h * 32;                                                   \
        u32 base = (u32)(nn) * KW2 + (u32)c * 8;                                 \
        uint4 hi0, hi1, lo0, lo1;                                                \
        hi0.x = pack_bf16(acc[0][h].x, acc[0][h].y);                             \
        hi0.y = pack_bf16(acc[1][h].x, acc[1][h].y);                             \
        hi0.z = pack_bf16(acc[2][h].x, acc[2][h].y);                             \
        hi0.w = pack_bf16(acc[3][h].x, acc[3][h].y);                             \
        hi1.x = pack_bf16(acc[4][h].x, acc[4][h].y);                             \
        hi1.y = pack_bf16(acc[5][h].x, acc[5][h].y);                             \
        hi1.z = pack_bf16(acc[6][h].x, acc[6][h].y);                             \
        hi1.w = pack_bf16(acc[7][h].x, acc[7][h].y);                             \
        lo0.x = pack_bf16(bf16_res(acc[0][h].x), bf16_res(acc[0][h].y));         \
        lo0.y = pack_bf16(bf16_res(acc[1][h].x), bf16_res(acc[1][h].y));         \
        lo0.z = pack_bf16(bf16_res(acc[2][h].x), bf16_res(acc[2][h].y));         \
        lo0.w = pack_bf16(bf16_res(acc[3][h].x), bf16_res(acc[3][h].y));         \
        lo1.x = pack_bf16(bf16_res(acc[4][h].x), bf16_res(acc[4][h].y));         \
        lo1.y = pack_bf16(bf16_res(acc[5][h].x), bf16_res(acc[5][h].y));         \
        lo1.z = pack_bf16(bf16_res(acc[6][h].x), bf16_res(acc[6][h].y));         \
        lo1.w = pack_bf16(bf16_res(acc[7][h].x), bf16_res(acc[7][h].y));         \
        *(uint4*)&g_A1[base]     = hi0;                                          \
        *(uint4*)&g_A1[base + 4] = hi1;                                          \
        *(uint4*)&g_A2[base]     = lo0;                                          \
        *(uint4*)&g_A2[base + 4] = lo1;                                          \
    }                                                                            \
} while (0)

// ---------------- gather 1: rigid weights -> wf0 -> A (bf16 split) ----------------
__global__ __launch_bounds__(TPB_G, 6) void gather1_kernel(
    const float* __restrict__ query, const float* __restrict__ support,
    const int* __restrict__ nbr, const float* __restrict__ feat,
    const float* __restrict__ kpts)
{
    __shared__ __align__(16) float s_w [PPB][NN][20];
    __shared__ int                 s_idx[PPB][NN];

    const int tid  = threadIdx.x;
    const int p    = tid >> 5;
    const int lane = tid & 31;
    const int n    = blockIdx.x * PPB + p;

    {
        float qx = query[n*3+0], qy = query[n*3+1], qz = query[n*3+2];
        for (int a = lane; a < NN; a += 32) {
            int id = nbr[n*NN + a];
            s_idx[p][a] = id;
            float px = support[id*3+0] - qx;
            float py = support[id*3+1] - qy;
            float pz = support[id*3+2] - qz;
            float wl[16];
            #pragma unroll
            for (int k = 0; k < KP; k++) {
                float dx = px - kpts[k*3+0];
                float dy = py - kpts[k*3+1];
                float dz = pz - kpts[k*3+2];
                float sq = dx*dx + dy*dy + dz*dz;
                wl[k] = fmaxf(1.0f - 2.0f * sqrtf(sq), 0.0f);
            }
            wl[15] = 0.0f;
            #pragma unroll
            for (int j = 0; j < 4; j++)
                *(float4*)&s_w[p][a][j*4] = make_float4(wl[j*4+0], wl[j*4+1], wl[j*4+2], wl[j*4+3]);
        }
    }
    __syncwarp();

    float2 acc[8][2];
    #pragma unroll
    for (int j = 0; j < 8; j++) { acc[j][0] = make_float2(0.f,0.f); acc[j][1] = make_float2(0.f,0.f); }

    GATHER_LOOP();
    STORE_A(n);
}

// ---------------- gather 2: deformed weights (+mod) -> wf -> A (bf16 split) ----------------
__global__ __launch_bounds__(TPB_G, 6) void gather2_kernel(
    const float* __restrict__ query, const float* __restrict__ support,
    const int* __restrict__ nbr, const float* __restrict__ feat)
{
    __shared__ __align__(16) float s_w  [PPB][NN][20];
    __shared__ int                 s_idx[PPB][NN];
    __shared__ __align__(16) float s_dkp[PPB][KP][4];

    const int tid  = threadIdx.x;
    const int p    = tid >> 5;
    const int lane = tid & 31;
    const int n    = blockIdx.x * PPB + p;

    if (lane < KP)
        *(float4*)&s_dkp[p][lane][0] = ((const float4*)g_dkp)[n * KP + lane];
    __syncwarp();

    {
        float qx = query[n*3+0], qy = query[n*3+1], qz = query[n*3+2];
        for (int a = lane; a < NN; a += 32) {
            int id = nbr[n*NN + a];
            s_idx[p][a] = id;
            float px = support[id*3+0] - qx;
            float py = support[id*3+1] - qy;
            float pz = support[id*3+2] - qz;
            float wl[16];
            #pragma unroll
            for (int k = 0; k < KP; k++) {
                float dx = px - s_dkp[p][k][0];
                float dy = py - s_dkp[p][k][1];
                float dz = pz - s_dkp[p][k][2];
                float sq = dx*dx + dy*dy + dz*dz;
                wl[k] = fmaxf(1.0f - 2.0f * sqrtf(sq), 0.0f);
            }
            wl[15] = 0.0f;
            #pragma unroll
            for (int j = 0; j < 4; j++)
                *(float4*)&s_w[p][a][j*4] = make_float4(wl[j*4+0], wl[j*4+1], wl[j*4+2], wl[j*4+3]);
        }
    }
    __syncwarp();

    float2 acc[8][2];
    #pragma unroll
    for (int j = 0; j < 8; j++) { acc[j][0] = make_float2(0.f,0.f); acc[j][1] = make_float2(0.f,0.f); }

    GATHER_LOOP();

    // apply modulations (k=15 slot forced to 0)
    #pragma unroll
    for (int j = 0; j < 8; j++) {
        float mx = s_dkp[p][2*j][3];
        float my = (j < 7) ? s_dkp[p][2*j+1][3] : 0.f;
        acc[j][0].x *= mx; acc[j][0].y *= my;
        acc[j][1].x *= mx; acc[j][1].y *= my;
    }
    STORE_A(n);
}

// ---------------- GEMM staging: cp.async one K-chunk into buffer ----------------
__device__ __forceinline__ void stage_chunk(const u32* __restrict__ B1g,
                                            const u32* __restrict__ B2g,
                                            int c, uint32_t smb, int buf,
                                            int tid, int pt0) {
    uint32_t base = smb + (uint32_t)buf * BUFSZ;
    #pragma unroll
    for (int it = 0; it < 4; it++) {
        int u = it * 256 + tid;
        int r = u >> 3, q = u & 7;
        uint32_t d = base + (uint32_t)(r * AS + q * 16);
        CP_ASYNC16(d + OFS_A1, g_A1 + (pt0 + r) * KW2 + c * 32 + q * 4);
        CP_ASYNC16(d + OFS_A2, g_A2 + (pt0 + r) * KW2 + c * 32 + q * 4);
    }
    #pragma unroll
    for (int it = 0; it < 2; it++) {
        int u = it * 256 + tid;
        int r = u >> 3, q = u & 7;
        uint32_t d = base + (uint32_t)(r * AS + q * 16);
        CP_ASYNC16(d + OFS_B1, B1g + r * KW2 + c * 32 + q * 4);
        CP_ASYNC16(d + OFS_B2, B2g + r * KW2 + c * 32 + q * 4);
    }
}

// ---------------- warp-MMA GEMM mainloop (double-buffered cp.async) ----------------
// D[128 x 64] = A[128 x 1024] * B[64 x 1024]^T, bf16 3-product split, 16 chunks of 64.
__device__ __forceinline__ void run_gemm_wm(const u32* __restrict__ B1g,
                                            const u32* __restrict__ B2g,
                                            char* smem, float* acc) {
    const int tid  = threadIdx.x;
    const int wid  = tid >> 5;
    const int lane = tid & 31;
    const int pt0  = blockIdx.x * MT;
    const uint32_t smb = smem_u32(smem);

    const uint32_t aoff = (uint32_t)(wid * 16 + (lane & 15)) * AS + ((lane >> 4) << 4);
    const uint32_t brow = (uint32_t)(((lane >> 4) << 3) + (lane & 7));
    const uint32_t boff = brow * AS + (((lane >> 3) & 1) << 4);

    #pragma unroll
    for (int i = 0; i < 32; i++) acc[i] = 0.f;

    stage_chunk(B1g, B2g, 0, smb, 0, tid, pt0);
    CP_COMMIT();

    int buf = 0;
    #pragma unroll 1
    for (int c = 0; c < NCHUNK; c++) {
        CP_WAIT0();
        __syncthreads();
        if (c + 1 < NCHUNK) {
            stage_chunk(B1g, B2g, c + 1, smb, buf ^ 1, tid, pt0);
            CP_COMMIT();
        }
        const uint32_t base = smb + (uint32_t)buf * BUFSZ;
        const uint32_t a1b = base + OFS_A1, a2b = base + OFS_A2;
        const uint32_t b1b = base + OFS_B1, b2b = base + OFS_B2;

        #pragma unroll
        for (int ks = 0; ks < 4; ks++) {
            const uint32_t kb = (uint32_t)(ks * 32);
            uint32_t a1[4], a2[4];
            LDSM_X4(a1, a1b + aoff + kb);
            LDSM_X4(a2, a2b + aoff + kb);
            #pragma unroll
            for (int nb2 = 0; nb2 < 4; nb2++) {
                uint32_t b1[4], b2[4];
                uint32_t bo = (uint32_t)(nb2 * 16) * AS + boff + kb;
                LDSM_X4(b1, b1b + bo);
                LDSM_X4(b2, b2b + bo);
                float* d0 = acc + (nb2 * 2) * 4;
                float* d1 = acc + (nb2 * 2 + 1) * 4;
                MMA_BF16(d0, a1, b1[0], b1[1]);
                MMA_BF16(d1, a1, b1[2], b1[3]);
                MMA_BF16(d0, a1, b2[0], b2[1]);
                MMA_BF16(d1, a1, b2[2], b2[3]);
                MMA_BF16(d0, a2, b1[0], b1[1]);
                MMA_BF16(d1, a2, b1[2], b1[3]);
            }
        }
        buf ^= 1;
    }
    __syncthreads();   // all warps done with smem before epilogue reuse
}

__device__ __forceinline__ void acc_to_smem(float* sx, const float* acc) {
    const int tid  = threadIdx.x;
    const int wid  = tid >> 5;
    const int lane = tid & 31;
    int r0 = wid * 16 + (lane >> 2);
    int cb = (lane & 3) * 2;
    #pragma unroll
    for (int nb = 0; nb < 8; nb++) {
        int col = nb * 8 + cb;
        sx[r0 * 68 + col]           = acc[nb * 4 + 0];
        sx[r0 * 68 + col + 1]       = acc[nb * 4 + 1];
        sx[(r0 + 8) * 68 + col]     = acc[nb * 4 + 2];
        sx[(r0 + 8) * 68 + col + 1] = acc[nb * 4 + 3];
    }
}

// ---------------- GEMM 1: f0 -> deformed kernel points + modulations ----------------
__global__ __launch_bounds__(256, 1) void gemm1_kernel(
    const float* __restrict__ obias, const float* __restrict__ kpts) {
    extern __shared__ __align__(16) char smem[];
    float acc[32];
    run_gemm_wm(g_OB1, g_OB2, smem, acc);

    float* sx = (float*)smem;
    acc_to_smem(sx, acc);
    __syncthreads();

    const int tid = threadIdx.x;
    if (tid < MT) {
        int n = blockIdx.x * MT + tid;
        float f0[60];
        #pragma unroll
        for (int i = 0; i < 60; i++) f0[i] = sx[tid * 68 + i] + obias[i];
        #pragma unroll
        for (int k = 0; k < KP; k++) {
            float4 o;
            o.x = kpts[k*3+0] + f0[3*k+0] * EXTENTF;
            o.y = kpts[k*3+1] + f0[3*k+1] * EXTENTF;
            o.z = kpts[k*3+2] + f0[3*k+2] * EXTENTF;
            o.w = 2.0f / (1.0f + expf(-f0[45 + k]));
            ((float4*)g_dkp)[n * KP + k] = o;
        }
    }
}

// ---------------- GEMM 2: x -> out + BN partials ----------------
__global__ __launch_bounds__(256, 1) void gemm2_kernel(float* __restrict__ out) {
    extern __shared__ __align__(16) char smem[];
    float acc[32];
    run_gemm_wm(g_WB1, g_WB2, smem, acc);

    float* sx = (float*)smem;
    acc_to_smem(sx, acc);
    __syncthreads();

    const int tid = threadIdx.x;
    {
        const int base4 = blockIdx.x * MT * OUTF / 4;
        for (int v = tid; v < MT * OUTF / 4; v += 256) {
            int pl = v >> 4, j = v & 15;
            float4 val = *(float4*)&sx[pl * 68 + j * 4];
            ((float4*)out)[base4 + v] = val;
        }
    }
    if (tid < OUTF) {
        float s = 0.f, s2 = 0.f;
        for (int pl = 0; pl < MT; pl++) {
            float v = sx[pl * 68 + tid];
            s += v; s2 += v * v;
        }
        g_psum  [blockIdx.x * OUTF + tid] = s;
        g_psumsq[blockIdx.x * OUTF + tid] = s2;
    }
}

// ---------------- BN stats ----------------
__global__ void stats_kernel(const float* __restrict__ gamma, const float* __restrict__ beta) {
    int o = blockIdx.x;
    int tid = threadIdx.x;
    float s = 0.f, s2 = 0.f;
    for (int j = tid; j < NGEMM; j += blockDim.x) {
        s  += g_psum  [j * OUTF + o];
        s2 += g_psumsq[j * OUTF + o];
    }
    __shared__ float sh[256], sh2[256];
    sh[tid] = s; sh2[tid] = s2;
    __syncthreads();
    for (int st = 128; st > 0; st >>= 1) {
        if (tid < st) { sh[tid] += sh[tid + st]; sh2[tid] += sh2[tid + st]; }
        __syncthreads();
    }
    if (tid == 0) {
        float mean = sh[0]  / (float)NPTS;
        float var  = sh2[0] / (float)NPTS - mean * mean;
        float sc   = rsqrtf(var + 1e-6f) * gamma[o];
        g_scale[o] = sc;
        g_shift[o] = beta[o] - mean * sc;
    }
}

// ---------------- BN apply + LeakyReLU ----------------
__global__ void bn_kernel(float* __restrict__ out) {
    const int total4 = NPTS * OUTF / 4;
    for (int i = blockIdx.x * blockDim.x + threadIdx.x; i < total4; i += gridDim.x * blockDim.x) {
        float4 v = ((float4*)out)[i];
        int ch = (i & 15) * 4;
        float4 sc = *(const float4*)&g_scale[ch];
        float4 sh = *(const float4*)&g_shift[ch];
        v.x = v.x * sc.x + sh.x;  v.x = v.x >= 0.f ? v.x : 0.1f * v.x;
        v.y = v.y * sc.y + sh.y;  v.y = v.y >= 0.f ? v.y : 0.1f * v.y;
        v.z = v.z * sc.z + sh.z;  v.z = v.z >= 0.f ? v.z : 0.1f * v.z;
        v.w = v.w * sc.w + sh.w;  v.w = v.w >= 0.f ? v.w : 0.1f * v.w;
        ((float4*)out)[i] = v;
    }
}

// ---------------- launch ----------------
extern "C" void kernel_launch(void* const* d_in, const int* in_sizes, int n_in,
                              void* d_out, int out_size) {
    const float* query   = (const float*)d_in[0];
    const float* support = (const float*)d_in[1];
    const int*   nbr     = (const int*)  d_in[2];
    const float* feat    = (const float*)d_in[3];
    const float* weight  = (const float*)d_in[4];
    const float* ow      = (const float*)d_in[5];
    const float* obias   = (const float*)d_in[6];
    const float* gamma   = (const float*)d_in[7];
    const float* beta    = (const float*)d_in[8];
    const float* kpts    = (const float*)d_in[9];
    float* out = (float*)d_out;

    static int attr_set = 0;
    if (!attr_set) {
        cudaFuncSetAttribute(gemm1_kernel, cudaFuncAttributeMaxDynamicSharedMemorySize, SM_GEMM);
        cudaFuncSetAttribute(gemm2_kernel, cudaFuncAttributeMaxDynamicSharedMemorySize, SM_GEMM);
        attr_set = 1;
    }

    prep_kernel   <<<64, 256>>>(ow, weight);
    gather1_kernel<<<NBLK_G, TPB_G>>>(query, support, nbr, feat, kpts);
    gemm1_kernel  <<<NGEMM, 256, SM_GEMM>>>(obias, kpts);
    gather2_kernel<<<NBLK_G, TPB_G>>>(query, support, nbr, feat);
    gemm2_kernel  <<<NGEMM, 256, SM_GEMM>>>(out);
    stats_kernel  <<<OUTF, 256>>>(gamma, beta);
    bn_kernel     <<<2048, 256>>>(out);
}

// round 15
// speedup vs baseline: 2.3261x; 1.0226x over previous
#include <cuda_runtime.h>
#include <cuda_bf16.h>
#include <math.h>
#include <stdint.h>

#define NPTS   65536
#define NN     34
#define KP     15
#define INF    64
#define OUTF   64
#define EXTENTF 0.5f
#define PPB    4                  // points per gather CTA (1 warp each)
#define TPB_G  128
#define NBLK_G (NPTS / PPB)       // 16384 gather CTAs
#define KW2    512                // u32 words per A/B row (bf16 pairs), K'=1024 (i' = c*16+k, k=15 pad)
#define MT     128                // GEMM tile M
#define NGEMM  (NPTS / MT)        // 512 GEMM CTAs
#define NCHUNK 16                 // 1024 / 64

// GEMM smem: padded tiles, row stride 144B (72 bf16) -> conflict-free ldmatrix
// Double-buffered: two 55296B buffers.
#define AS      144
#define OFS_A1  0
#define OFS_A2  18432
#define OFS_B1  36864
#define OFS_B2  46080
#define BUFSZ   55296
#define SM_GEMM (2 * BUFSZ)       // 110592 B

typedef unsigned long long u64;
typedef unsigned int u32;

// ---------------- device scratch ----------------
__device__ __align__(16) u32 g_A1[NPTS * KW2];    // wf hi  (bf16 pairs, i' = c*16+k)
__device__ __align__(16) u32 g_A2[NPTS * KW2];    // wf residual
__device__ __align__(16) u32 g_OB1[64 * KW2];     // offset_weight^T hi [d][i'] pairs
__device__ __align__(16) u32 g_OB2[64 * KW2];
__device__ __align__(16) u32 g_WB1[64 * KW2];     // weight^T hi [o][i'] pairs
__device__ __align__(16) u32 g_WB2[64 * KW2];
__device__ __align__(16) float g_dkp[NPTS * KP * 4];  // deformed kp xyz + modulation
__device__ float g_psum  [NGEMM * OUTF];
__device__ float g_psumsq[NGEMM * OUTF];
__device__ __align__(16) float g_scale[OUTF];
__device__ __align__(16) float g_shift[OUTF];

// ---------------- helpers ----------------
__device__ __forceinline__ void f2fma(float2 &acc, float2 a, float2 b) {
    asm("{\n\t"
        ".reg .b64 ra, rb, rc;\n\t"
        "mov.b64 ra, {%2, %3};\n\t"
        "mov.b64 rb, {%4, %5};\n\t"
        "mov.b64 rc, {%0, %1};\n\t"
        "fma.rn.f32x2 rc, ra, rb, rc;\n\t"
        "mov.b64 {%0, %1}, rc;\n\t"
        "}"
        : "+f"(acc.x), "+f"(acc.y)
        : "f"(a.x), "f"(a.y), "f"(b.x), "f"(b.y));
}

__device__ __forceinline__ uint32_t smem_u32(const void* p) {
    uint32_t a;
    asm("{ .reg .u64 t; cvta.to.shared.u64 t, %1; cvt.u32.u64 %0, t; }" : "=r"(a) : "l"(p));
    return a;
}

#define CP_ASYNC16(dst, src)                                                      \
    asm volatile("{ .reg .u64 g; cvta.to.global.u64 g, %1; "                      \
                 "cp.async.cg.shared.global [%0], [g], 16; }"                     \
                 :: "r"(dst), "l"(src) : "memory")
#define CP_COMMIT() asm volatile("cp.async.commit_group;" ::: "memory")
#define CP_WAIT0()  asm volatile("cp.async.wait_group 0;" ::: "memory")

#define LDSM_X4(r, addr)                                                          \
    asm volatile("ldmatrix.sync.aligned.m8n8.x4.shared.b16 {%0,%1,%2,%3}, [%4];"  \
        : "=r"((r)[0]), "=r"((r)[1]), "=r"((r)[2]), "=r"((r)[3]) : "r"(addr))

#define MMA_BF16(d, a, b0, b1)                                                    \
    asm volatile("mma.sync.aligned.m16n8k16.row.col.f32.bf16.bf16.f32 "           \
        "{%0,%1,%2,%3}, {%4,%5,%6,%7}, {%8,%9}, {%0,%1,%2,%3};"                   \
        : "+f"((d)[0]), "+f"((d)[1]), "+f"((d)[2]), "+f"((d)[3])                  \
        : "r"((a)[0]), "r"((a)[1]), "r"((a)[2]), "r"((a)[3]), "r"(b0), "r"(b1))

__device__ __forceinline__ u32 pack_bf16(float lo, float hi) {
    __nv_bfloat162 h = __floats2bfloat162_rn(lo, hi);
    return *(u32*)&h;
}
__device__ __forceinline__ float bf16_res(float v) {
    return v - __bfloat162float(__float2bfloat16_rn(v));
}

// ---------------- prep: hi/lo bf16 transposed weight matrices, i' = c*16+k order ----------------
__global__ void prep_kernel(const float* __restrict__ ow, const float* __restrict__ w) {
    int t = blockIdx.x * blockDim.x + threadIdx.x;
    int stride = gridDim.x * blockDim.x;
    for (int idx = t; idx < 64 * KW2; idx += stride) {
        int row = idx / KW2, j = idx - row * KW2;
        int ip0 = 2 * j, ip1 = 2 * j + 1;
        int c0 = ip0 >> 4, k0 = ip0 & 15;
        int c1 = ip1 >> 4, k1 = ip1 & 15;
        // offset_weight [i=k*64+c][d=60]
        float v0 = (k0 < 15 && row < 60) ? ow[(k0 * 64 + c0) * 60 + row] : 0.f;
        float v1 = (k1 < 15 && row < 60) ? ow[(k1 * 64 + c1) * 60 + row] : 0.f;
        g_OB1[idx] = pack_bf16(v0, v1);
        g_OB2[idx] = pack_bf16(bf16_res(v0), bf16_res(v1));
        // weight [i=k*64+c][o=64]
        float u0 = (k0 < 15) ? w[(k0 * 64 + c0) * 64 + row] : 0.f;
        float u1 = (k1 < 15) ? w[(k1 * 64 + c1) * 64 + row] : 0.f;
        g_WB1[idx] = pack_bf16(u0, u1);
        g_WB2[idx] = pack_bf16(bf16_res(u0), bf16_res(u1));
    }
}

// ---------------- gather FMA block: 16 FFMA2 on one weight row ----------------
// lane owns channels c0=2*lane (h=0) and c0+1 (h=1)
#define WROW16(a_cur, f_cur) do {                                                \
    float2 ff0 = make_float2((f_cur).x, (f_cur).x);                              \
    float2 ff1 = make_float2((f_cur).y, (f_cur).y);                              \
    const float4* wr = (const float4*)&s_w[p][a_cur][0];                         \
    float4 w0 = wr[0], w1 = wr[1], w2 = wr[2], w3 = wr[3];                       \
    f2fma(acc[0][0], make_float2(w0.x, w0.y), ff0);                              \
    f2fma(acc[0][1], make_float2(w0.x, w0.y), ff1);                              \
    f2fma(acc[1][0], make_float2(w0.z, w0.w), ff0);                              \
    f2fma(acc[1][1], make_float2(w0.z, w0.w), ff1);                              \
    f2fma(acc[2][0], make_float2(w1.x, w1.y), ff0);                              \
    f2fma(acc[2][1], make_float2(w1.x, w1.y), ff1);                              \
    f2fma(acc[3][0], make_float2(w1.z, w1.w), ff0);                              \
    f2fma(acc[3][1], make_float2(w1.z, w1.w), ff1);                              \
    f2fma(acc[4][0], make_float2(w2.x, w2.y), ff0);                              \
    f2fma(acc[4][1], make_float2(w2.x, w2.y), ff1);                              \
    f2fma(acc[5][0], make_float2(w2.z, w2.w), ff0);                              \
    f2fma(acc[5][1], make_float2(w2.z, w2.w), ff1);                              \
    f2fma(acc[6][0], make_float2(w3.x, w3.y), ff0);                              \
    f2fma(acc[6][1], make_float2(w3.x, w3.y), ff1);                              \
    f2fma(acc[7][0], make_float2(w3.z, w3.w), ff0);                              \
    f2fma(acc[7][1], make_float2(w3.z, w3.w), ff1);                              \
} while (0)

// sparse gather loop over compacted nonzero-row list, 1-deep prefetch
#define SPARSE_GATHER_LOOP() do {                                                \
    if (cnt > 0) {                                                               \
        int a_nx = s_list[p][0];                                                 \
        float2 f_nx = *(const float2*)&feat[(size_t)s_idx[p][a_nx] * INF + 2 * lane]; \
        for (int i = 0; i < cnt; i++) {                                          \
            int a_cur = a_nx;                                                    \
            float2 f_cur = f_nx;                                                 \
            if (i + 1 < cnt) {                                                   \
                a_nx = s_list[p][i + 1];                                         \
                f_nx = *(const float2*)&feat[(size_t)s_idx[p][a_nx] * INF + 2 * lane]; \
            }                                                                    \
            WROW16(a_cur, f_cur);                                                \
        }                                                                        \
    }                                                                            \
} while (0)

// direct bf16 hi/res pack + store: lane writes 8 pairs per channel (c = 2*lane+h)
#define STORE_A(nn) do {                                                         \
    _Pragma("unroll")                                                            \
    for (int h = 0; h < 2; h++) {                                                \
        int c = 2 * lane + h;                                                    \
        u32 base = (u32)(nn) * KW2 + (u32)c * 8;                                 \
        uint4 hi0, hi1, lo0, lo1;                                                \
        hi0.x = pack_bf16(acc[0][h].x, acc[0][h].y);                             \
        hi0.y = pack_bf16(acc[1][h].x, acc[1][h].y);                             \
        hi0.z = pack_bf16(acc[2][h].x, acc[2][h].y);                             \
        hi0.w = pack_bf16(acc[3][h].x, acc[3][h].y);                             \
        hi1.x = pack_bf16(acc[4][h].x, acc[4][h].y);                             \
        hi1.y = pack_bf16(acc[5][h].x, acc[5][h].y);                             \
        hi1.z = pack_bf16(acc[6][h].x, acc[6][h].y);                             \
        hi1.w = pack_bf16(acc[7][h].x, acc[7][h].y);                             \
        lo0.x = pack_bf16(bf16_res(acc[0][h].x), bf16_res(acc[0][h].y));         \
        lo0.y = pack_bf16(bf16_res(acc[1][h].x), bf16_res(acc[1][h].y));         \
        lo0.z = pack_bf16(bf16_res(acc[2][h].x), bf16_res(acc[2][h].y));         \
        lo0.w = pack_bf16(bf16_res(acc[3][h].x), bf16_res(acc[3][h].y));         \
        lo1.x = pack_bf16(bf16_res(acc[4][h].x), bf16_res(acc[4][h].y));         \
        lo1.y = pack_bf16(bf16_res(acc[5][h].x), bf16_res(acc[5][h].y));         \
        lo1.z = pack_bf16(bf16_res(acc[6][h].x), bf16_res(acc[6][h].y));         \
        lo1.w = pack_bf16(bf16_res(acc[7][h].x), bf16_res(acc[7][h].y));         \
        *(uint4*)&g_A1[base]     = hi0;                                          \
        *(uint4*)&g_A1[base + 4] = hi1;                                          \
        *(uint4*)&g_A2[base]     = lo0;                                          \
        *(uint4*)&g_A2[base + 4] = lo1;                                          \
    }                                                                            \
} while (0)

// build compact list of nonzero rows from row-max values mA (a=lane) and mB (a=lane+32, lanes 0/1)
#define BUILD_LIST() do {                                                        \
    u32 b0 = __ballot_sync(0xffffffffu, mA > 0.f);                               \
    u32 b1 = __ballot_sync(0xffffffffu, (lane < 2) && (mB > 0.f));               \
    u32 below = (lane == 0) ? 0u : (0xffffffffu >> (32 - lane));                 \
    int posA = __popc(b0 & below);                                               \
    if (mA > 0.f) s_list[p][posA] = lane;                                        \
    int baseB = __popc(b0);                                                      \
    if ((lane < 2) && (mB > 0.f))                                                \
        s_list[p][baseB + __popc(b1 & below)] = lane + 32;                       \
    cnt = baseB + __popc(b1);                                                    \
} while (0)

// ---------------- gather 1: rigid weights -> wf0 -> A (bf16 split) ----------------
__global__ __launch_bounds__(TPB_G, 6) void gather1_kernel(
    const float* __restrict__ query, const float* __restrict__ support,
    const int* __restrict__ nbr, const float* __restrict__ feat,
    const float* __restrict__ kpts)
{
    __shared__ __align__(16) float s_w [PPB][NN][20];
    __shared__ int                 s_idx[PPB][NN];
    __shared__ int                 s_list[PPB][NN + 2];

    const int tid  = threadIdx.x;
    const int p    = tid >> 5;
    const int lane = tid & 31;
    const int n    = blockIdx.x * PPB + p;
    int cnt;

    {
        float qx = query[n*3+0], qy = query[n*3+1], qz = query[n*3+2];
        // row A: a = lane
        float mA;
        {
            int id = nbr[n*NN + lane];
            s_idx[p][lane] = id;
            float px = support[id*3+0] - qx;
            float py = support[id*3+1] - qy;
            float pz = support[id*3+2] - qz;
            float wl[16]; float m = 0.f;
            #pragma unroll
            for (int k = 0; k < KP; k++) {
                float dx = px - kpts[k*3+0];
                float dy = py - kpts[k*3+1];
                float dz = pz - kpts[k*3+2];
                float sq = dx*dx + dy*dy + dz*dz;
                wl[k] = fmaxf(1.0f - 2.0f * sqrtf(sq), 0.0f);
                m = fmaxf(m, wl[k]);
            }
            wl[15] = 0.0f;
            #pragma unroll
            for (int j = 0; j < 4; j++)
                *(float4*)&s_w[p][lane][j*4] = make_float4(wl[j*4+0], wl[j*4+1], wl[j*4+2], wl[j*4+3]);
            mA = m;
        }
        // row B: a = lane+32 (valid lanes 0,1)
        float mB = 0.f;
        {
            bool valid = (lane < 2);
            int id = valid ? nbr[n*NN + 32 + lane] : 0;
            float px = support[id*3+0] - qx;
            float py = support[id*3+1] - qy;
            float pz = support[id*3+2] - qz;
            float wl[16]; float m = 0.f;
            #pragma unroll
            for (int k = 0; k < KP; k++) {
                float dx = px - kpts[k*3+0];
                float dy = py - kpts[k*3+1];
                float dz = pz - kpts[k*3+2];
                float sq = dx*dx + dy*dy + dz*dz;
                wl[k] = fmaxf(1.0f - 2.0f * sqrtf(sq), 0.0f);
                m = fmaxf(m, wl[k]);
            }
            wl[15] = 0.0f;
            if (valid) {
                s_idx[p][32 + lane] = id;
                #pragma unroll
                for (int j = 0; j < 4; j++)
                    *(float4*)&s_w[p][32 + lane][j*4] = make_float4(wl[j*4+0], wl[j*4+1], wl[j*4+2], wl[j*4+3]);
                mB = m;
            }
        }
        BUILD_LIST();
    }
    __syncwarp();

    float2 acc[8][2];
    #pragma unroll
    for (int j = 0; j < 8; j++) { acc[j][0] = make_float2(0.f,0.f); acc[j][1] = make_float2(0.f,0.f); }

    SPARSE_GATHER_LOOP();
    STORE_A(n);
}

// ---------------- gather 2: deformed weights (+mod) -> wf -> A (bf16 split) ----------------
__global__ __launch_bounds__(TPB_G, 6) void gather2_kernel(
    const float* __restrict__ query, const float* __restrict__ support,
    const int* __restrict__ nbr, const float* __restrict__ feat)
{
    __shared__ __align__(16) float s_w  [PPB][NN][20];
    __shared__ int                 s_idx[PPB][NN];
    __shared__ int                 s_list[PPB][NN + 2];
    __shared__ __align__(16) float s_dkp[PPB][KP][4];

    const int tid  = threadIdx.x;
    const int p    = tid >> 5;
    const int lane = tid & 31;
    const int n    = blockIdx.x * PPB + p;
    int cnt;

    if (lane < KP)
        *(float4*)&s_dkp[p][lane][0] = ((const float4*)g_dkp)[n * KP + lane];
    __syncwarp();

    {
        float qx = query[n*3+0], qy = query[n*3+1], qz = query[n*3+2];
        float mA;
        {
            int id = nbr[n*NN + lane];
            s_idx[p][lane] = id;
            float px = support[id*3+0] - qx;
            float py = support[id*3+1] - qy;
            float pz = support[id*3+2] - qz;
            float wl[16]; float m = 0.f;
            #pragma unroll
            for (int k = 0; k < KP; k++) {
                float dx = px - s_dkp[p][k][0];
                float dy = py - s_dkp[p][k][1];
                float dz = pz - s_dkp[p][k][2];
                float sq = dx*dx + dy*dy + dz*dz;
                wl[k] = fmaxf(1.0f - 2.0f * sqrtf(sq), 0.0f);
                m = fmaxf(m, wl[k]);
            }
            wl[15] = 0.0f;
            #pragma unroll
            for (int j = 0; j < 4; j++)
                *(float4*)&s_w[p][lane][j*4] = make_float4(wl[j*4+0], wl[j*4+1], wl[j*4+2], wl[j*4+3]);
            mA = m;
        }
        float mB = 0.f;
        {
            bool valid = (lane < 2);
            int id = valid ? nbr[n*NN + 32 + lane] : 0;
            float px = support[id*3+0] - qx;
            float py = support[id*3+1] - qy;
            float pz = support[id*3+2] - qz;
            float wl[16]; float m = 0.f;
            #pragma unroll
            for (int k = 0; k < KP; k++) {
                float dx = px - s_dkp[p][k][0];
                float dy = py - s_dkp[p][k][1];
                float dz = pz - s_dkp[p][k][2];
                float sq = dx*dx + dy*dy + dz*dz;
                wl[k] = fmaxf(1.0f - 2.0f * sqrtf(sq), 0.0f);
                m = fmaxf(m, wl[k]);
            }
            wl[15] = 0.0f;
            if (valid) {
                s_idx[p][32 + lane] = id;
                #pragma unroll
                for (int j = 0; j < 4; j++)
                    *(float4*)&s_w[p][32 + lane][j*4] = make_float4(wl[j*4+0], wl[j*4+1], wl[j*4+2], wl[j*4+3]);
                mB = m;
            }
        }
        BUILD_LIST();
    }
    __syncwarp();

    float2 acc[8][2];
    #pragma unroll
    for (int j = 0; j < 8; j++) { acc[j][0] = make_float2(0.f,0.f); acc[j][1] = make_float2(0.f,0.f); }

    SPARSE_GATHER_LOOP();

    // apply modulations: acc[j][h] holds k-pairs (2j, 2j+1) for channel 2*lane+h
    #pragma unroll
    for (int j = 0; j < 8; j++) {
        float mx = s_dkp[p][2*j][3];
        float my = (j < 7) ? s_dkp[p][2*j+1][3] : 0.f;
        acc[j][0].x *= mx; acc[j][0].y *= my;
        acc[j][1].x *= mx; acc[j][1].y *= my;
    }
    STORE_A(n);
}

// ---------------- GEMM staging: cp.async one K-chunk into buffer ----------------
__device__ __forceinline__ void stage_chunk(const u32* __restrict__ B1g,
                                            const u32* __restrict__ B2g,
                                            int c, uint32_t smb, int buf,
                                            int tid, int pt0) {
    uint32_t base = smb + (uint32_t)buf * BUFSZ;
    #pragma unroll
    for (int it = 0; it < 4; it++) {
        int u = it * 256 + tid;
        int r = u >> 3, q = u & 7;
        uint32_t d = base + (uint32_t)(r * AS + q * 16);
        CP_ASYNC16(d + OFS_A1, g_A1 + (pt0 + r) * KW2 + c * 32 + q * 4);
        CP_ASYNC16(d + OFS_A2, g_A2 + (pt0 + r) * KW2 + c * 32 + q * 4);
    }
    #pragma unroll
    for (int it = 0; it < 2; it++) {
        int u = it * 256 + tid;
        int r = u >> 3, q = u & 7;
        uint32_t d = base + (uint32_t)(r * AS + q * 16);
        CP_ASYNC16(d + OFS_B1, B1g + r * KW2 + c * 32 + q * 4);
        CP_ASYNC16(d + OFS_B2, B2g + r * KW2 + c * 32 + q * 4);
    }
}

// ---------------- warp-MMA GEMM mainloop (double-buffered cp.async) ----------------
// D[128 x 64] = A[128 x 1024] * B[64 x 1024]^T, bf16 3-product split, 16 chunks of 64.
__device__ __forceinline__ void run_gemm_wm(const u32* __restrict__ B1g,
                                            const u32* __restrict__ B2g,
                                            char* smem, float* acc) {
    const int tid  = threadIdx.x;
    const int wid  = tid >> 5;
    const int lane = tid & 31;
    const int pt0  = blockIdx.x * MT;
    const uint32_t smb = smem_u32(smem);

    const uint32_t aoff = (uint32_t)(wid * 16 + (lane & 15)) * AS + ((lane >> 4) << 4);
    const uint32_t brow = (uint32_t)(((lane >> 4) << 3) + (lane & 7));
    const uint32_t boff = brow * AS + (((lane >> 3) & 1) << 4);

    #pragma unroll
    for (int i = 0; i < 32; i++) acc[i] = 0.f;

    stage_chunk(B1g, B2g, 0, smb, 0, tid, pt0);
    CP_COMMIT();

    int buf = 0;
    #pragma unroll 1
    for (int c = 0; c < NCHUNK; c++) {
        CP_WAIT0();
        __syncthreads();
        if (c + 1 < NCHUNK) {
            stage_chunk(B1g, B2g, c + 1, smb, buf ^ 1, tid, pt0);
            CP_COMMIT();
        }
        const uint32_t base = smb + (uint32_t)buf * BUFSZ;
        const uint32_t a1b = base + OFS_A1, a2b = base + OFS_A2;
        const uint32_t b1b = base + OFS_B1, b2b = base + OFS_B2;

        #pragma unroll
        for (int ks = 0; ks < 4; ks++) {
            const uint32_t kb = (uint32_t)(ks * 32);
            uint32_t a1[4], a2[4];
            LDSM_X4(a1, a1b + aoff + kb);
            LDSM_X4(a2, a2b + aoff + kb);
            #pragma unroll
            for (int nb2 = 0; nb2 < 4; nb2++) {
                uint32_t b1[4], b2[4];
                uint32_t bo = (uint32_t)(nb2 * 16) * AS + boff + kb;
                LDSM_X4(b1, b1b + bo);
                LDSM_X4(b2, b2b + bo);
                float* d0 = acc + (nb2 * 2) * 4;
                float* d1 = acc + (nb2 * 2 + 1) * 4;
                MMA_BF16(d0, a1, b1[0], b1[1]);
                MMA_BF16(d1, a1, b1[2], b1[3]);
                MMA_BF16(d0, a1, b2[0], b2[1]);
                MMA_BF16(d1, a1, b2[2], b2[3]);
                MMA_BF16(d0, a2, b1[0], b1[1]);
                MMA_BF16(d1, a2, b1[2], b1[3]);
            }
        }
        buf ^= 1;
    }
    __syncthreads();   // all warps done with smem before epilogue reuse
}

__device__ __forceinline__ void acc_to_smem(float* sx, const float* acc) {
    const int tid  = threadIdx.x;
    const int wid  = tid >> 5;
    const int lane = tid & 31;
    int r0 = wid * 16 + (lane >> 2);
    int cb = (lane & 3) * 2;
    #pragma unroll
    for (int nb = 0; nb < 8; nb++) {
        int col = nb * 8 + cb;
        sx[r0 * 68 + col]           = acc[nb * 4 + 0];
        sx[r0 * 68 + col + 1]       = acc[nb * 4 + 1];
        sx[(r0 + 8) * 68 + col]     = acc[nb * 4 + 2];
        sx[(r0 + 8) * 68 + col + 1] = acc[nb * 4 + 3];
    }
}

// ---------------- GEMM 1: f0 -> deformed kernel points + modulations ----------------
__global__ __launch_bounds__(256, 1) void gemm1_kernel(
    const float* __restrict__ obias, const float* __restrict__ kpts) {
    extern __shared__ __align__(16) char smem[];
    float acc[32];
    run_gemm_wm(g_OB1, g_OB2, smem, acc);

    float* sx = (float*)smem;
    acc_to_smem(sx, acc);
    __syncthreads();

    const int tid = threadIdx.x;
    if (tid < MT) {
        int n = blockIdx.x * MT + tid;
        float f0[60];
        #pragma unroll
        for (int i = 0; i < 60; i++) f0[i] = sx[tid * 68 + i] + obias[i];
        #pragma unroll
        for (int k = 0; k < KP; k++) {
            float4 o;
            o.x = kpts[k*3+0] + f0[3*k+0] * EXTENTF;
            o.y = kpts[k*3+1] + f0[3*k+1] * EXTENTF;
            o.z = kpts[k*3+2] + f0[3*k+2] * EXTENTF;
            o.w = 2.0f / (1.0f + expf(-f0[45 + k]));
            ((float4*)g_dkp)[n * KP + k] = o;
        }
    }
}

// ---------------- GEMM 2: x -> out + BN partials ----------------
__global__ __launch_bounds__(256, 1) void gemm2_kernel(float* __restrict__ out) {
    extern __shared__ __align__(16) char smem[];
    float acc[32];
    run_gemm_wm(g_WB1, g_WB2, smem, acc);

    float* sx = (float*)smem;
    acc_to_smem(sx, acc);
    __syncthreads();

    const int tid = threadIdx.x;
    {
        const int base4 = blockIdx.x * MT * OUTF / 4;
        for (int v = tid; v < MT * OUTF / 4; v += 256) {
            int pl = v >> 4, j = v & 15;
            float4 val = *(float4*)&sx[pl * 68 + j * 4];
            ((float4*)out)[base4 + v] = val;
        }
    }
    if (tid < OUTF) {
        float s = 0.f, s2 = 0.f;
        for (int pl = 0; pl < MT; pl++) {
            float v = sx[pl * 68 + tid];
            s += v; s2 += v * v;
        }
        g_psum  [blockIdx.x * OUTF + tid] = s;
        g_psumsq[blockIdx.x * OUTF + tid] = s2;
    }
}

// ---------------- BN stats ----------------
__global__ void stats_kernel(const float* __restrict__ gamma, const float* __restrict__ beta) {
    int o = blockIdx.x;
    int tid = threadIdx.x;
    float s = 0.f, s2 = 0.f;
    for (int j = tid; j < NGEMM; j += blockDim.x) {
        s  += g_psum  [j * OUTF + o];
        s2 += g_psumsq[j * OUTF + o];
    }
    __shared__ float sh[256], sh2[256];
    sh[tid] = s; sh2[tid] = s2;
    __syncthreads();
    for (int st = 128; st > 0; st >>= 1) {
        if (tid < st) { sh[tid] += sh[tid + st]; sh2[tid] += sh2[tid + st]; }
        __syncthreads();
    }
    if (tid == 0) {
        float mean = sh[0]  / (float)NPTS;
        float var  = sh2[0] / (float)NPTS - mean * mean;
        float sc   = rsqrtf(var + 1e-6f) * gamma[o];
        g_scale[o] = sc;
        g_shift[o] = beta[o] - mean * sc;
    }
}

// ---------------- BN apply + LeakyReLU ----------------
__global__ void bn_kernel(float* __restrict__ out) {
    const int total4 = NPTS * OUTF / 4;
    for (int i = blockIdx.x * blockDim.x + threadIdx.x; i < total4; i += gridDim.x * blockDim.x) {
        float4 v = ((float4*)out)[i];
        int ch = (i & 15) * 4;
        float4 sc = *(const float4*)&g_scale[ch];
        float4 sh = *(const float4*)&g_shift[ch];
        v.x = v.x * sc.x + sh.x;  v.x = v.x >= 0.f ? v.x : 0.1f * v.x;
        v.y = v.y * sc.y + sh.y;  v.y = v.y >= 0.f ? v.y : 0.1f * v.y;
        v.z = v.z * sc.z + sh.z;  v.z = v.z >= 0.f ? v.z : 0.1f * v.z;
        v.w = v.w * sc.w + sh.w;  v.w = v.w >= 0.f ? v.w : 0.1f * v.w;
        ((float4*)out)[i] = v;
    }
}

// ---------------- launch ----------------
extern "C" void kernel_launch(void* const* d_in, const int* in_sizes, int n_in,
                              void* d_out, int out_size) {
    const float* query   = (const float*)d_in[0];
    const float* support = (const float*)d_in[1];
    const int*   nbr     = (const int*)  d_in[2];
    const float* feat    = (const float*)d_in[3];
    const float* weight  = (const float*)d_in[4];
    const float* ow      = (const float*)d_in[5];
    const float* obias   = (const float*)d_in[6];
    const float* gamma   = (const float*)d_in[7];
    const float* beta    = (const float*)d_in[8];
    const float* kpts    = (const float*)d_in[9];
    float* out = (float*)d_out;

    static int attr_set = 0;
    if (!attr_set) {
        cudaFuncSetAttribute(gemm1_kernel, cudaFuncAttributeMaxDynamicSharedMemorySize, SM_GEMM);
        cudaFuncSetAttribute(gemm2_kernel, cudaFuncAttributeMaxDynamicSharedMemorySize, SM_GEMM);
        attr_set = 1;
    }

    prep_kernel   <<<64, 256>>>(ow, weight);
    gather1_kernel<<<NBLK_G, TPB_G>>>(query, support, nbr, feat, kpts);
    gemm1_kernel  <<<NGEMM, 256, SM_GEMM>>>(obias, kpts);
    gather2_kernel<<<NBLK_G, TPB_G>>>(query, support, nbr, feat);
    gemm2_kernel  <<<NGEMM, 256, SM_GEMM>>>(out);
    stats_kernel  <<<OUTF, 256>>>(gamma, beta);
    bn_kernel     <<<2048, 256>>>(out);
}